// round 7
// baseline (speedup 1.0000x reference)
#include <cuda_runtime.h>
#include <cmath>
#include <cstdint>

// ---------------- problem constants ----------------
#define HID   2048
#define SEQL  1024
#define NBAT  4
#define NHEAD 16
#define DHEAD 128
#define MTOK  4096          // NBAT*SEQL
#define BHTOT 64            // NBAT*NHEAD

#define MF ((size_t)1048576)

// ---------------- single flat scratch: 176M floats = 704MB ------------------
__device__ __align__(16) float g_scratch[176 * MF];

#define OFF_Y     (0 * MF)
#define OFF_QKV   (8 * MF)
#define OFF_Q     (32 * MF)
#define OFF_K     (40 * MF)
#define OFF_VT    (48 * MF)
#define OFF_S     (56 * MF)
#define OFF_W1R   (56 * MF)     // aliases S (rounded after S's last read)
#define OFF_W2R   (72 * MF)     // aliases S
#define OFF_CTX   (120 * MF)
#define OFF_CTXR  (128 * MF)
#define OFF_X2    (136 * MF)
#define OFF_MLP   (144 * MF)
#define OFF_WQKVR (144 * MF)    // aliases mlp (mlp written at step 10)
#define OFF_WOR   (156 * MF)    // aliases mlp

__device__ __forceinline__ float f2tf32f(float f) {
    unsigned u;
    asm("cvt.rna.tf32.f32 %0, %1;" : "=r"(u) : "f"(f));
    return __uint_as_float(u);
}

#define BKP 36                 // padded K stride (bank-conflict free, 16B aligned)

// ================= big-tile GEMM: 128x256 block, 64x64 warp tile ===========
// C[m,n] = epilogue( alpha * sum_k A[m,k]*B[n,k] ), A: MxK, B: NxK (tf32-pre-rounded)
#define BM2 128
#define BN2 256
#define BK2 32
#define STAGE2_F ((BM2 + BN2) * BKP)               // floats per stage
#define GEMM2_SMEM (3 * STAGE2_F * 4)              // 3 stages = 165888 B

// MODE 0: C = a*acc   1: +rscale*resid   2: round(gelu_us(a*acc+b))   3: a*acc+b+resid
template <int MODE>
__global__ void __launch_bounds__(256, 1)
gemm_big(const float* __restrict__ A, const float* __restrict__ B,
         float* __restrict__ C,
         int M, int N, int K,
         long sA, long sB, long sC,
         float alpha,
         const float* __restrict__ bias, float bscale,
         const float* __restrict__ resid, float rscale,
         float inv_rms)
{
    extern __shared__ float smem[];

    const int m0 = blockIdx.y * BM2;
    const int n0 = blockIdx.x * BN2;
    A += blockIdx.z * sA + (long)m0 * K;
    B += blockIdx.z * sB + (long)n0 * K;
    C += blockIdx.z * sC;
    const float* Rz = (MODE == 1 || MODE == 3) ? resid + blockIdx.z * sC : nullptr;

    const int tid  = threadIdx.x;
    const int lane = tid & 31;
    const int warp = tid >> 5;
    const int wm = warp >> 2;          // 0..1  (64 rows each)
    const int wn = warp & 3;           // 0..3  (64 cols each)
    const int g  = lane >> 2;          // 0..7
    const int t4 = lane & 3;           // 0..3

    float acc[4][8][4];
#pragma unroll
    for (int i = 0; i < 4; i++)
#pragma unroll
        for (int j = 0; j < 8; j++)
#pragma unroll
            for (int c = 0; c < 4; c++) acc[i][j][c] = 0.f;

    const int KT = K / BK2;

    auto issue = [&](int kt, int buf) {
        float* Sb = smem + buf * STAGE2_F;
        const long kof = (long)kt * BK2;
        // 3072 16B-chunks: A rows [0,128) then B rows [0,256), 12 per thread
#pragma unroll
        for (int q = 0; q < 12; q++) {
            int idx = tid + q * 256;
            if (idx < 1024) {
                int r = idx >> 3, c = (idx & 7) * 4;
                unsigned d = (unsigned)__cvta_generic_to_shared(&Sb[r * BKP + c]);
                asm volatile("cp.async.cg.shared.global [%0], [%1], 16;\n"
                             :: "r"(d), "l"(A + (long)r * K + kof + c) : "memory");
            } else {
                int j = idx - 1024;
                int r = j >> 3, c = (j & 7) * 4;
                unsigned d = (unsigned)__cvta_generic_to_shared(&Sb[(BM2 + r) * BKP + c]);
                asm volatile("cp.async.cg.shared.global [%0], [%1], 16;\n"
                             :: "r"(d), "l"(B + (long)r * K + kof + c) : "memory");
            }
        }
        asm volatile("cp.async.commit_group;\n" ::: "memory");
    };

    issue(0, 0);
    issue(1, 1);

    int buf = 0;
    for (int kt = 0; kt < KT; kt++) {
        if (kt + 1 < KT) {
            asm volatile("cp.async.wait_group 1;\n" ::: "memory");
        } else {
            asm volatile("cp.async.wait_group 0;\n" ::: "memory");
        }
        __syncthreads();   // stage kt visible to all; all warps done with kt-1
        if (kt + 2 < KT) {
            int lb = buf + 2; if (lb >= 3) lb -= 3;
            issue(kt + 2, lb);
        }

        const float* Asb = smem + buf * STAGE2_F;
        const float* Bsb = Asb + (size_t)BM2 * BKP;

#pragma unroll
        for (int ks = 0; ks < 4; ks++) {
            const int kb = ks * 8;
            unsigned af[4][4], bf[8][2];
#pragma unroll
            for (int mt = 0; mt < 4; mt++) {
                int r = wm * 64 + mt * 16;
                af[mt][0] = __float_as_uint(Asb[(r + g    ) * BKP + kb + t4]);
                af[mt][1] = __float_as_uint(Asb[(r + g + 8) * BKP + kb + t4]);
                af[mt][2] = __float_as_uint(Asb[(r + g    ) * BKP + kb + t4 + 4]);
                af[mt][3] = __float_as_uint(Asb[(r + g + 8) * BKP + kb + t4 + 4]);
            }
#pragma unroll
            for (int nt = 0; nt < 8; nt++) {
                int c = wn * 64 + nt * 8;
                bf[nt][0] = __float_as_uint(Bsb[(c + g) * BKP + kb + t4]);
                bf[nt][1] = __float_as_uint(Bsb[(c + g) * BKP + kb + t4 + 4]);
            }
#pragma unroll
            for (int mt = 0; mt < 4; mt++)
#pragma unroll
                for (int nt = 0; nt < 8; nt++) {
                    asm volatile(
                        "mma.sync.aligned.m16n8k8.row.col.f32.tf32.tf32.f32 "
                        "{%0,%1,%2,%3}, {%4,%5,%6,%7}, {%8,%9}, {%0,%1,%2,%3};\n"
                        : "+f"(acc[mt][nt][0]), "+f"(acc[mt][nt][1]),
                          "+f"(acc[mt][nt][2]), "+f"(acc[mt][nt][3])
                        : "r"(af[mt][0]), "r"(af[mt][1]), "r"(af[mt][2]), "r"(af[mt][3]),
                          "r"(bf[nt][0]), "r"(bf[nt][1]));
                }
        }
        buf++; if (buf == 3) buf = 0;
    }

    // ---------------- epilogue ----------------
#pragma unroll
    for (int mt = 0; mt < 4; mt++) {
        int rbase = m0 + wm * 64 + mt * 16;
#pragma unroll
        for (int nt = 0; nt < 8; nt++) {
            int c0 = n0 + wn * 64 + nt * 8 + 2 * t4;
#pragma unroll
            for (int half = 0; half < 2; half++) {
                int r = rbase + g + half * 8;
                float v0 = acc[mt][nt][half * 2 + 0] * alpha;
                float v1 = acc[mt][nt][half * 2 + 1] * alpha;
                if (MODE == 2 || MODE == 3) {
                    v0 += bias[c0] * bscale;
                    v1 += bias[c0 + 1] * bscale;
                }
                if (MODE == 2) {
                    v0 = f2tf32f(v0 * normcdff(v0) * inv_rms);
                    v1 = f2tf32f(v1 * normcdff(v1) * inv_rms);
                }
                long idx = (long)r * N + c0;
                if (MODE == 1 || MODE == 3) {
                    float2 rv = *(const float2*)(Rz + idx);
                    v0 += rv.x * rscale;
                    v1 += rv.y * rscale;
                }
                *(float2*)(C + idx) = make_float2(v0, v1);
            }
        }
    }
}

// ================= 128x128 GEMM (for ctx: N=128) ============================
#define BM 128
#define BN 128
#define BK 32
#define STAGE_F (BM * BKP)
#define GEMM_SMEM_BYTES (4 * STAGE_F * 4)  // 73728 B

template <int MODE>
__global__ void __launch_bounds__(256, 2)
gemm_tn(const float* __restrict__ A, const float* __restrict__ B,
        float* __restrict__ C,
        int M, int N, int K,
        long sA, long sB, long sC,
        float alpha,
        const float* __restrict__ bias, float bscale,
        const float* __restrict__ resid, float rscale,
        float inv_rms)
{
    extern __shared__ float smem[];
    float* As = smem;
    float* Bs = smem + 2 * STAGE_F;

    const int m0 = blockIdx.y * BM;
    const int n0 = blockIdx.x * BN;
    A += blockIdx.z * sA + (long)m0 * K;
    B += blockIdx.z * sB + (long)n0 * K;
    C += blockIdx.z * sC;
    const float* Rz = (MODE == 1 || MODE == 3) ? resid + blockIdx.z * sC : nullptr;

    const int tid  = threadIdx.x;
    const int lane = tid & 31;
    const int warp = tid >> 5;
    const int wm = warp >> 2;
    const int wn = warp & 3;
    const int g  = lane >> 2;
    const int t4 = lane & 3;

    const int lrow = tid >> 3;
    const int lcol = (tid & 7) * 4;

    float acc[4][4][4];
#pragma unroll
    for (int i = 0; i < 4; i++)
#pragma unroll
        for (int j = 0; j < 4; j++)
#pragma unroll
            for (int c = 0; c < 4; c++) acc[i][j][c] = 0.f;

    const int KT = K / BK;

    auto issue = [&](int kt, int buf) {
        const float* Ag = A + kt * BK;
        const float* Bg = B + kt * BK;
        float* Asb = As + buf * STAGE_F;
        float* Bsb = Bs + buf * STAGE_F;
#pragma unroll
        for (int i = 0; i < 4; i++) {
            int r = lrow + i * 32;
            unsigned da = (unsigned)__cvta_generic_to_shared(&Asb[r * BKP + lcol]);
            asm volatile("cp.async.cg.shared.global [%0], [%1], 16;\n"
                         :: "r"(da), "l"(Ag + (long)r * K + lcol) : "memory");
            unsigned db = (unsigned)__cvta_generic_to_shared(&Bsb[r * BKP + lcol]);
            asm volatile("cp.async.cg.shared.global [%0], [%1], 16;\n"
                         :: "r"(db), "l"(Bg + (long)r * K + lcol) : "memory");
        }
        asm volatile("cp.async.commit_group;\n" ::: "memory");
    };

    issue(0, 0);

    for (int kt = 0; kt < KT; kt++) {
        int buf = kt & 1;
        asm volatile("cp.async.wait_group 0;\n" ::: "memory");
        __syncthreads();
        if (kt + 1 < KT) issue(kt + 1, buf ^ 1);

        const float* Asb = As + buf * STAGE_F;
        const float* Bsb = Bs + buf * STAGE_F;

#pragma unroll
        for (int ks = 0; ks < 4; ks++) {
            const int kb = ks * 8;
            unsigned af[4][4], bf[4][2];
#pragma unroll
            for (int mt = 0; mt < 4; mt++) {
                int r = wm * 64 + mt * 16;
                af[mt][0] = __float_as_uint(Asb[(r + g    ) * BKP + kb + t4]);
                af[mt][1] = __float_as_uint(Asb[(r + g + 8) * BKP + kb + t4]);
                af[mt][2] = __float_as_uint(Asb[(r + g    ) * BKP + kb + t4 + 4]);
                af[mt][3] = __float_as_uint(Asb[(r + g + 8) * BKP + kb + t4 + 4]);
            }
#pragma unroll
            for (int nt = 0; nt < 4; nt++) {
                int c = wn * 32 + nt * 8;
                bf[nt][0] = __float_as_uint(Bsb[(c + g) * BKP + kb + t4]);
                bf[nt][1] = __float_as_uint(Bsb[(c + g) * BKP + kb + t4 + 4]);
            }
#pragma unroll
            for (int mt = 0; mt < 4; mt++)
#pragma unroll
                for (int nt = 0; nt < 4; nt++) {
                    asm volatile(
                        "mma.sync.aligned.m16n8k8.row.col.f32.tf32.tf32.f32 "
                        "{%0,%1,%2,%3}, {%4,%5,%6,%7}, {%8,%9}, {%0,%1,%2,%3};\n"
                        : "+f"(acc[mt][nt][0]), "+f"(acc[mt][nt][1]),
                          "+f"(acc[mt][nt][2]), "+f"(acc[mt][nt][3])
                        : "r"(af[mt][0]), "r"(af[mt][1]), "r"(af[mt][2]), "r"(af[mt][3]),
                          "r"(bf[nt][0]), "r"(bf[nt][1]));
                }
        }
        __syncthreads();
    }

#pragma unroll
    for (int mt = 0; mt < 4; mt++) {
        int rbase = m0 + wm * 64 + mt * 16;
#pragma unroll
        for (int nt = 0; nt < 4; nt++) {
            int c0 = n0 + wn * 32 + nt * 8 + 2 * t4;
#pragma unroll
            for (int half = 0; half < 2; half++) {
                int r = rbase + g + half * 8;
                float v0 = acc[mt][nt][half * 2 + 0] * alpha;
                float v1 = acc[mt][nt][half * 2 + 1] * alpha;
                if (MODE == 2 || MODE == 3) {
                    v0 += bias[c0] * bscale;
                    v1 += bias[c0 + 1] * bscale;
                }
                if (MODE == 2) {
                    v0 = f2tf32f(v0 * normcdff(v0) * inv_rms);
                    v1 = f2tf32f(v1 * normcdff(v1) * inv_rms);
                }
                long idx = (long)r * N + c0;
                if (MODE == 1 || MODE == 3) {
                    float2 rv = *(const float2*)(Rz + idx);
                    v0 += rv.x * rscale;
                    v1 += rv.y * rscale;
                }
                *(float2*)(C + idx) = make_float2(v0, v1);
            }
        }
    }
}

// ---------------- LayerNorm (rounds output to tf32) -------------------------
__global__ void ln_kernel(const float* __restrict__ xin,
                          const float* __restrict__ w,
                          const float* __restrict__ b,
                          float* __restrict__ y)
{
    __shared__ float red[16];
    const long row = blockIdx.x;
    const float4* xr = (const float4*)(xin + row * HID);
    const int t = threadIdx.x;

    float4 v0 = xr[t];
    float4 v1 = xr[t + 256];
    float s  = v0.x + v0.y + v0.z + v0.w + v1.x + v1.y + v1.z + v1.w;
    float sq = v0.x*v0.x + v0.y*v0.y + v0.z*v0.z + v0.w*v0.w
             + v1.x*v1.x + v1.y*v1.y + v1.z*v1.z + v1.w*v1.w;
#pragma unroll
    for (int o = 16; o; o >>= 1) {
        s  += __shfl_xor_sync(0xffffffffu, s,  o);
        sq += __shfl_xor_sync(0xffffffffu, sq, o);
    }
    if ((t & 31) == 0) { red[t >> 5] = s; red[8 + (t >> 5)] = sq; }
    __syncthreads();
    if (t == 0) {
        float S = 0.f, Q = 0.f;
        for (int i = 0; i < 8; i++) { S += red[i]; Q += red[8 + i]; }
        red[0] = S; red[8] = Q;
    }
    __syncthreads();
    const float mean = red[0] * (1.0f / HID);
    float var = red[8] * (1.0f / HID) - mean * mean;
    var = fmaxf(var, 0.0f);
    const float rstd = rsqrtf(var + 1e-5f);

    float4* yr = (float4*)(y + row * HID);
    const float4 w0 = ((const float4*)w)[t];
    const float4 w1 = ((const float4*)w)[t + 256];
    const float4 b0 = ((const float4*)b)[t];
    const float4 b1 = ((const float4*)b)[t + 256];
    float4 o0, o1;
    o0.x = f2tf32f((v0.x - mean) * rstd * w0.x + b0.x);
    o0.y = f2tf32f((v0.y - mean) * rstd * w0.y + b0.y);
    o0.z = f2tf32f((v0.z - mean) * rstd * w0.z + b0.z);
    o0.w = f2tf32f((v0.w - mean) * rstd * w0.w + b0.w);
    o1.x = f2tf32f((v1.x - mean) * rstd * w1.x + b1.x);
    o1.y = f2tf32f((v1.y - mean) * rstd * w1.y + b1.y);
    o1.z = f2tf32f((v1.z - mean) * rstd * w1.z + b1.z);
    o1.w = f2tf32f((v1.w - mean) * rstd * w1.w + b1.w);
    yr[t]       = o0;
    yr[t + 256] = o1;
}

// ---------------- softmax (rounds probs to tf32) ----------------------------
__global__ void softmax_kernel(float* __restrict__ sc)
{
    __shared__ float red[16];
    const size_t row = blockIdx.x;
    float4* p = (float4*)(sc + row * (size_t)SEQL);
    const int t = threadIdx.x;

    float4 v = p[t];
    float mx = fmaxf(fmaxf(v.x, v.y), fmaxf(v.z, v.w));
#pragma unroll
    for (int o = 16; o; o >>= 1) mx = fmaxf(mx, __shfl_xor_sync(0xffffffffu, mx, o));
    if ((t & 31) == 0) red[t >> 5] = mx;
    __syncthreads();
    if (t == 0) {
        float m = red[0];
        for (int i = 1; i < 8; i++) m = fmaxf(m, red[i]);
        red[0] = m;
    }
    __syncthreads();
    mx = red[0];

    float e0 = expf(v.x - mx), e1 = expf(v.y - mx);
    float e2 = expf(v.z - mx), e3 = expf(v.w - mx);
    float s = e0 + e1 + e2 + e3;
#pragma unroll
    for (int o = 16; o; o >>= 1) s += __shfl_xor_sync(0xffffffffu, s, o);
    if ((t & 31) == 0) red[8 + (t >> 5)] = s;
    __syncthreads();
    if (t == 0) {
        float S = 0.f;
        for (int i = 0; i < 8; i++) S += red[8 + i];
        red[8] = S;
    }
    __syncthreads();
    const float inv = 1.0f / red[8];

    float4 o;
    o.x = f2tf32f(e0 * inv); o.y = f2tf32f(e1 * inv);
    o.z = f2tf32f(e2 * inv); o.w = f2tf32f(e3 * inv);
    p[t] = o;
}

// ---------------- pack qkv -> Q[bh,s,d], K[bh,s,d], Vt[bh,d,s] (rounded) ----
__global__ void pack_qkv(const float* __restrict__ qkv,
                         float* __restrict__ Qd, float* __restrict__ Kd,
                         float* __restrict__ Vtd)
{
    const int t = blockIdx.x * 256 + threadIdx.x;
    const int d  = t & 127;
    const int s  = (t >> 7) & 1023;
    const int bh = t >> 17;
    const int b  = bh >> 4, h = bh & 15;
    const long m = (long)b * SEQL + s;
    const long base = m * (3 * HID) + (long)h * DHEAD + d;
    const long o = (long)bh * (SEQL * DHEAD) + (long)s * DHEAD + d;
    Qd[o] = f2tf32f(qkv[base]);
    Kd[o] = f2tf32f(qkv[base + HID]);
    Vtd[(long)bh * (SEQL * DHEAD) + (long)d * SEQL + s] = f2tf32f(qkv[base + 2 * HID]);
}

// ---------------- repack ctx[bh,s,d] -> ctxr[b*s, h*d] (rounded) ------------
__global__ void repack_ctx(const float* __restrict__ ctx, float* __restrict__ ctxr)
{
    const int t = blockIdx.x * 256 + threadIdx.x;
    const int hc = t & 2047;
    const int m  = t >> 11;
    const int d = hc & 127, h = hc >> 7;
    const int b = m >> 10, s = m & 1023;
    ctxr[t] = f2tf32f(
        ctx[((long)(b * NHEAD + h)) * (SEQL * DHEAD) + (long)s * DHEAD + d]);
}

// ---------------- weight rounding to tf32 -----------------------------------
__global__ void round_w(const float4* __restrict__ in, float4* __restrict__ out, int n4)
{
    int i = blockIdx.x * 256 + threadIdx.x;
    if (i < n4) {
        float4 v = in[i];
        v.x = f2tf32f(v.x); v.y = f2tf32f(v.y);
        v.z = f2tf32f(v.z); v.w = f2tf32f(v.w);
        out[i] = v;
    }
}

// ---------------- launch ----------------------------------------------------
extern "C" void kernel_launch(void* const* d_in, const int* in_sizes, int n_in,
                              void* d_out, int out_size)
{
    const float* x    = (const float*)d_in[0];
    const float* ln1w = (const float*)d_in[1];
    const float* ln1b = (const float*)d_in[2];
    const float* wqkv = (const float*)d_in[3];
    const float* wo   = (const float*)d_in[4];
    const float* ln2w = (const float*)d_in[5];
    const float* ln2b = (const float*)d_in[6];
    const float* w1   = (const float*)d_in[7];
    const float* b1   = (const float*)d_in[8];
    const float* w2   = (const float*)d_in[9];
    const float* b2   = (const float*)d_in[10];
    float* out = (float*)d_out;

    // GELU_RMS via the same quadrature as the reference
    double ssum = 0.0;
    const double dx = 24.0 / 48000.0;
    for (int i = 0; i <= 48000; i++) {
        double xx  = -12.0 + dx * i;
        double pdf = exp(-0.5 * xx * xx) / sqrt(2.0 * M_PI);
        double cdf = 0.5 * (1.0 + erf(xx / sqrt(2.0)));
        double gg  = xx * cdf;
        ssum += gg * gg * pdf;
    }
    const float inv_rms = (float)(1.0 / sqrt(ssum * dx));

    float* base;
    cudaGetSymbolAddress((void**)&base, g_scratch);
    float* py     = base + OFF_Y;
    float* pqkv   = base + OFF_QKV;
    float* pQ     = base + OFF_Q;
    float* pK     = base + OFF_K;
    float* pVt    = base + OFF_VT;
    float* pS     = base + OFF_S;
    float* pw1r   = base + OFF_W1R;
    float* pw2r   = base + OFF_W2R;
    float* pctx   = base + OFF_CTX;
    float* pctxr  = base + OFF_CTXR;
    float* px2    = base + OFF_X2;
    float* pmlp   = base + OFF_MLP;
    float* pwqkvr = base + OFF_WQKVR;
    float* pwor   = base + OFF_WOR;

    cudaFuncSetAttribute(gemm_big<0>, cudaFuncAttributeMaxDynamicSharedMemorySize, GEMM2_SMEM);
    cudaFuncSetAttribute(gemm_big<1>, cudaFuncAttributeMaxDynamicSharedMemorySize, GEMM2_SMEM);
    cudaFuncSetAttribute(gemm_big<2>, cudaFuncAttributeMaxDynamicSharedMemorySize, GEMM2_SMEM);
    cudaFuncSetAttribute(gemm_big<3>, cudaFuncAttributeMaxDynamicSharedMemorySize, GEMM2_SMEM);
    cudaFuncSetAttribute(gemm_tn<0>, cudaFuncAttributeMaxDynamicSharedMemorySize, GEMM_SMEM_BYTES);

    const float rs_h  = (float)(1.0 / sqrt((double)HID));
    const float rs_d  = (float)(1.0 / sqrt((double)DHEAD));
    const float a_ctx = (float)(32.0 / exp(0.5));
    const float a_o   = (float)(sqrt(0.01) / sqrt((double)HID));
    const float r_o   = (float)sqrt(0.99);
    const float a_w2  = (float)(sqrt(0.5) / sqrt((double)(4 * HID)));
    const float b_w2  = (float)sqrt(0.5);
    const float r_w2  = (float)sqrt(0.5);

    // 0. round wqkv/wo to tf32 (into mlp-region aliases; free until step 10)
    round_w<<<(3 * HID * HID / 4 + 255) / 256, 256>>>((const float4*)wqkv, (float4*)pwqkvr, 3 * HID * HID / 4);
    round_w<<<(HID * HID / 4 + 255) / 256, 256>>>((const float4*)wo, (float4*)pwor, HID * HID / 4);

    // 1. LN1 (tf32-rounded output)
    ln_kernel<<<MTOK, 256>>>(x, ln1w, ln1b, py);
    // 2. QKV = LN1(x) @ Wqkv^T * h^-0.5      [4096 x 6144]
    gemm_big<0><<<dim3(24, 32, 1), 256, GEMM2_SMEM>>>(
        py, pwqkvr, pqkv, MTOK, 3 * HID, HID, 0, 0, 0,
        rs_h, nullptr, 0.f, nullptr, 0.f, 0.f);
    // 3. pack Q/K/Vt (rounded)
    pack_qkv<<<32768, 256>>>(pqkv, pQ, pK, pVt);
    // 4. scores = Q K^T * d^-0.5             [64 x 1024 x 1024]
    gemm_big<0><<<dim3(4, 8, BHTOT), 256, GEMM2_SMEM>>>(
        pQ, pK, pS, SEQL, SEQL, DHEAD,
        (long)SEQL * DHEAD, (long)SEQL * DHEAD, (long)SEQL * SEQL,
        rs_d, nullptr, 0.f, nullptr, 0.f, 0.f);
    // 5. softmax (rounded probs)
    softmax_kernel<<<BHTOT * SEQL, 256>>>(pS);
    // 6. ctx = P @ V * sqrt(S)/sqrt(e)       [64 x 1024 x 128] (N=128 kernel)
    gemm_tn<0><<<dim3(1, 8, BHTOT), 256, GEMM_SMEM_BYTES>>>(
        pS, pVt, pctx, SEQL, DHEAD, SEQL,
        (long)SEQL * SEQL, (long)SEQL * DHEAD, (long)SEQL * DHEAD,
        a_ctx, nullptr, 0.f, nullptr, 0.f, 0.f);
    // 6.5 scores no longer needed: round w1/w2 into the S region
    round_w<<<(4 * HID * HID / 4 + 255) / 256, 256>>>((const float4*)w1, (float4*)pw1r, 4 * HID * HID / 4);
    round_w<<<(4 * HID * HID / 4 + 255) / 256, 256>>>((const float4*)w2, (float4*)pw2r, 4 * HID * HID / 4);
    // 7. repack ctx (rounded)
    repack_ctx<<<32768, 256>>>(pctx, pctxr);
    // 8. x2 = (ctx @ Wo^T)*h^-0.5*sqrt(tau) + x*sqrt(1-tau)
    gemm_big<1><<<dim3(8, 32, 1), 256, GEMM2_SMEM>>>(
        pctxr, pwor, px2, MTOK, HID, HID, 0, 0, 0,
        a_o, nullptr, 0.f, x, r_o, 0.f);
    // 9. LN2 (rounded output)
    ln_kernel<<<MTOK, 256>>>(px2, ln2w, ln2b, py);
    // 10. mlp = gelu_us( LN2 @ W1^T * h^-0.5 + b1 )
    gemm_big<2><<<dim3(32, 32, 1), 256, GEMM2_SMEM>>>(
        py, pw1r, pmlp, MTOK, 4 * HID, HID, 0, 0, 0,
        rs_h, b1, 1.0f, nullptr, 0.f, inv_rms);
    // 11. out = (mlp @ W2^T * (4h)^-0.5 + b2)*sqrt(.5) + x2*sqrt(.5)
    gemm_big<3><<<dim3(8, 32, 1), 256, GEMM2_SMEM>>>(
        pmlp, pw2r, out, MTOK, HID, 4 * HID, 0, 0, 0,
        a_w2, b2, b_w2, px2, r_w2, 0.f);
}

// round 8
// speedup vs baseline: 1.0544x; 1.0544x over previous
#include <cuda_runtime.h>
#include <cmath>
#include <cstdint>

// ---------------- problem constants ----------------
#define HID   2048
#define SEQL  1024
#define NBAT  4
#define NHEAD 16
#define DHEAD 128
#define MTOK  4096          // NBAT*SEQL
#define BHTOT 64            // NBAT*NHEAD

#define MF ((size_t)1048576)

// ---------------- single flat scratch: 176M floats = 704MB ------------------
__device__ __align__(16) float g_scratch[176 * MF];

#define OFF_Y     (0 * MF)
#define OFF_QKV   (8 * MF)
#define OFF_Q     (32 * MF)
#define OFF_K     (40 * MF)
#define OFF_VT    (48 * MF)
#define OFF_S     (56 * MF)
#define OFF_W1R   (56 * MF)     // aliases S (rounded after S's last read)
#define OFF_W2R   (72 * MF)     // aliases S
#define OFF_CTX   (120 * MF)
#define OFF_CTXR  (128 * MF)
#define OFF_X2    (136 * MF)
#define OFF_MLP   (144 * MF)
#define OFF_WQKVR (144 * MF)    // aliases mlp (mlp written at step 10)
#define OFF_WOR   (156 * MF)    // aliases mlp

__device__ __forceinline__ float f2tf32f(float f) {
    unsigned u;
    asm("cvt.rna.tf32.f32 %0, %1;" : "=r"(u) : "f"(f));
    return __uint_as_float(u);
}

// ---------------- GEMM: 128x128 block, 4 warps, 64x64 warp tile -------------
// C[m,n] = epilogue( alpha * sum_k A[m,k]*B[n,k] )  (A: MxK, B: NxK, tf32-pre-rounded)
// 3 CTAs/SM (reg-capped), 2-stage cp.async, ONE barrier per k-tile.
#define BKP 36
#define STG_F ((128 + 128) * BKP)          // 9216 floats per stage
#define GEMM_SMEM (2 * STG_F * 4)          // 73728 B

// MODE 0: C = a*acc   1: +rscale*resid   2: round(gelu_us(a*acc+b))   3: a*acc+b+resid
template <int MODE>
__global__ void __launch_bounds__(128, 3)
gemm_tn(const float* __restrict__ A, const float* __restrict__ B,
        float* __restrict__ C,
        int M, int N, int K,
        long sA, long sB, long sC,
        float alpha,
        const float* __restrict__ bias, float bscale,
        const float* __restrict__ resid, float rscale,
        float inv_rms)
{
    extern __shared__ float smem[];

    const int m0 = blockIdx.y * 128;
    const int n0 = blockIdx.x * 128;
    A += blockIdx.z * sA + (long)m0 * K;
    B += blockIdx.z * sB + (long)n0 * K;
    C += blockIdx.z * sC;
    const float* Rz = (MODE == 1 || MODE == 3) ? resid + blockIdx.z * sC : nullptr;

    const int tid  = threadIdx.x;
    const int lane = tid & 31;
    const int warp = tid >> 5;
    const int wm = warp >> 1;          // 0..1 (64 rows)
    const int wn = warp & 1;           // 0..1 (64 cols)
    const int g  = lane >> 2;          // 0..7
    const int t4 = lane & 3;           // 0..3

    float acc[4][8][4];
#pragma unroll
    for (int i = 0; i < 4; i++)
#pragma unroll
        for (int j = 0; j < 8; j++)
#pragma unroll
            for (int c = 0; c < 4; c++) acc[i][j][c] = 0.f;

    const int KT = K / 32;

    auto issue = [&](int kt, int buf) {
        float* Sb = smem + buf * STG_F;
        const long kof = (long)kt * 32;
        // 2048 16B chunks: A rows [0,128) then B rows [0,128); 16 per thread
#pragma unroll
        for (int q = 0; q < 16; q++) {
            int idx = tid + q * 128;
            if (idx < 1024) {
                int r = idx >> 3, c = (idx & 7) * 4;
                unsigned d = (unsigned)__cvta_generic_to_shared(&Sb[r * BKP + c]);
                asm volatile("cp.async.cg.shared.global [%0], [%1], 16;\n"
                             :: "r"(d), "l"(A + (long)r * K + kof + c) : "memory");
            } else {
                int j = idx - 1024;
                int r = j >> 3, c = (j & 7) * 4;
                unsigned d = (unsigned)__cvta_generic_to_shared(&Sb[(128 + r) * BKP + c]);
                asm volatile("cp.async.cg.shared.global [%0], [%1], 16;\n"
                             :: "r"(d), "l"(B + (long)r * K + kof + c) : "memory");
            }
        }
        asm volatile("cp.async.commit_group;\n" ::: "memory");
    };

    issue(0, 0);

    for (int kt = 0; kt < KT; kt++) {
        const int buf = kt & 1;
        asm volatile("cp.async.wait_group 0;\n" ::: "memory");
        __syncthreads();   // stage kt visible; all warps finished stage kt-1 (same buffer as kt+1's target)
        if (kt + 1 < KT) issue(kt + 1, buf ^ 1);

        const float* Asb = smem + buf * STG_F;
        const float* Bsb = Asb + 128 * BKP;

#pragma unroll
        for (int ks = 0; ks < 4; ks++) {
            const int kb = ks * 8;
            unsigned af[4][4];
#pragma unroll
            for (int mt = 0; mt < 4; mt++) {
                int r = wm * 64 + mt * 16;
                af[mt][0] = __float_as_uint(Asb[(r + g    ) * BKP + kb + t4]);
                af[mt][1] = __float_as_uint(Asb[(r + g + 8) * BKP + kb + t4]);
                af[mt][2] = __float_as_uint(Asb[(r + g    ) * BKP + kb + t4 + 4]);
                af[mt][3] = __float_as_uint(Asb[(r + g + 8) * BKP + kb + t4 + 4]);
            }
#pragma unroll
            for (int nt = 0; nt < 8; nt++) {
                int c = wn * 64 + nt * 8;
                unsigned b0 = __float_as_uint(Bsb[(c + g) * BKP + kb + t4]);
                unsigned b1 = __float_as_uint(Bsb[(c + g) * BKP + kb + t4 + 4]);
#pragma unroll
                for (int mt = 0; mt < 4; mt++) {
                    asm volatile(
                        "mma.sync.aligned.m16n8k8.row.col.f32.tf32.tf32.f32 "
                        "{%0,%1,%2,%3}, {%4,%5,%6,%7}, {%8,%9}, {%0,%1,%2,%3};\n"
                        : "+f"(acc[mt][nt][0]), "+f"(acc[mt][nt][1]),
                          "+f"(acc[mt][nt][2]), "+f"(acc[mt][nt][3])
                        : "r"(af[mt][0]), "r"(af[mt][1]), "r"(af[mt][2]), "r"(af[mt][3]),
                          "r"(b0), "r"(b1));
                }
            }
        }
    }

    // ---------------- epilogue ----------------
#pragma unroll
    for (int mt = 0; mt < 4; mt++) {
        int rbase = m0 + wm * 64 + mt * 16;
#pragma unroll
        for (int nt = 0; nt < 8; nt++) {
            int c0 = n0 + wn * 64 + nt * 8 + 2 * t4;
#pragma unroll
            for (int half = 0; half < 2; half++) {
                int r = rbase + g + half * 8;
                float v0 = acc[mt][nt][half * 2 + 0] * alpha;
                float v1 = acc[mt][nt][half * 2 + 1] * alpha;
                if (MODE == 2 || MODE == 3) {
                    v0 += bias[c0] * bscale;
                    v1 += bias[c0 + 1] * bscale;
                }
                if (MODE == 2) {
                    v0 = f2tf32f(v0 * normcdff(v0) * inv_rms);
                    v1 = f2tf32f(v1 * normcdff(v1) * inv_rms);
                }
                long idx = (long)r * N + c0;
                if (MODE == 1 || MODE == 3) {
                    float2 rv = *(const float2*)(Rz + idx);
                    v0 += rv.x * rscale;
                    v1 += rv.y * rscale;
                }
                *(float2*)(C + idx) = make_float2(v0, v1);
            }
        }
    }
}

// ---------------- LayerNorm (rounds output to tf32) -------------------------
__global__ void ln_kernel(const float* __restrict__ xin,
                          const float* __restrict__ w,
                          const float* __restrict__ b,
                          float* __restrict__ y)
{
    __shared__ float red[16];
    const long row = blockIdx.x;
    const float4* xr = (const float4*)(xin + row * HID);
    const int t = threadIdx.x;

    float4 v0 = xr[t];
    float4 v1 = xr[t + 256];
    float s  = v0.x + v0.y + v0.z + v0.w + v1.x + v1.y + v1.z + v1.w;
    float sq = v0.x*v0.x + v0.y*v0.y + v0.z*v0.z + v0.w*v0.w
             + v1.x*v1.x + v1.y*v1.y + v1.z*v1.z + v1.w*v1.w;
#pragma unroll
    for (int o = 16; o; o >>= 1) {
        s  += __shfl_xor_sync(0xffffffffu, s,  o);
        sq += __shfl_xor_sync(0xffffffffu, sq, o);
    }
    if ((t & 31) == 0) { red[t >> 5] = s; red[8 + (t >> 5)] = sq; }
    __syncthreads();
    if (t == 0) {
        float S = 0.f, Q = 0.f;
        for (int i = 0; i < 8; i++) { S += red[i]; Q += red[8 + i]; }
        red[0] = S; red[8] = Q;
    }
    __syncthreads();
    const float mean = red[0] * (1.0f / HID);
    float var = red[8] * (1.0f / HID) - mean * mean;
    var = fmaxf(var, 0.0f);
    const float rstd = rsqrtf(var + 1e-5f);

    float4* yr = (float4*)(y + row * HID);
    const float4 w0 = ((const float4*)w)[t];
    const float4 w1 = ((const float4*)w)[t + 256];
    const float4 b0 = ((const float4*)b)[t];
    const float4 b1 = ((const float4*)b)[t + 256];
    float4 o0, o1;
    o0.x = f2tf32f((v0.x - mean) * rstd * w0.x + b0.x);
    o0.y = f2tf32f((v0.y - mean) * rstd * w0.y + b0.y);
    o0.z = f2tf32f((v0.z - mean) * rstd * w0.z + b0.z);
    o0.w = f2tf32f((v0.w - mean) * rstd * w0.w + b0.w);
    o1.x = f2tf32f((v1.x - mean) * rstd * w1.x + b1.x);
    o1.y = f2tf32f((v1.y - mean) * rstd * w1.y + b1.y);
    o1.z = f2tf32f((v1.z - mean) * rstd * w1.z + b1.z);
    o1.w = f2tf32f((v1.w - mean) * rstd * w1.w + b1.w);
    yr[t]       = o0;
    yr[t + 256] = o1;
}

// ---------------- softmax (rounds probs to tf32) ----------------------------
__global__ void softmax_kernel(float* __restrict__ sc)
{
    __shared__ float red[16];
    const size_t row = blockIdx.x;
    float4* p = (float4*)(sc + row * (size_t)SEQL);
    const int t = threadIdx.x;

    float4 v = p[t];
    float mx = fmaxf(fmaxf(v.x, v.y), fmaxf(v.z, v.w));
#pragma unroll
    for (int o = 16; o; o >>= 1) mx = fmaxf(mx, __shfl_xor_sync(0xffffffffu, mx, o));
    if ((t & 31) == 0) red[t >> 5] = mx;
    __syncthreads();
    if (t == 0) {
        float m = red[0];
        for (int i = 1; i < 8; i++) m = fmaxf(m, red[i]);
        red[0] = m;
    }
    __syncthreads();
    mx = red[0];

    float e0 = expf(v.x - mx), e1 = expf(v.y - mx);
    float e2 = expf(v.z - mx), e3 = expf(v.w - mx);
    float s = e0 + e1 + e2 + e3;
#pragma unroll
    for (int o = 16; o; o >>= 1) s += __shfl_xor_sync(0xffffffffu, s, o);
    if ((t & 31) == 0) red[8 + (t >> 5)] = s;
    __syncthreads();
    if (t == 0) {
        float S = 0.f;
        for (int i = 0; i < 8; i++) S += red[8 + i];
        red[8] = S;
    }
    __syncthreads();
    const float inv = 1.0f / red[8];

    float4 o;
    o.x = f2tf32f(e0 * inv); o.y = f2tf32f(e1 * inv);
    o.z = f2tf32f(e2 * inv); o.w = f2tf32f(e3 * inv);
    p[t] = o;
}

// ---------------- pack qkv -> Q[bh,s,d], K[bh,s,d], Vt[bh,d,s] (rounded) ----
__global__ void pack_qkv(const float* __restrict__ qkv,
                         float* __restrict__ Qd, float* __restrict__ Kd,
                         float* __restrict__ Vtd)
{
    const int t = blockIdx.x * 256 + threadIdx.x;
    const int d  = t & 127;
    const int s  = (t >> 7) & 1023;
    const int bh = t >> 17;
    const int b  = bh >> 4, h = bh & 15;
    const long m = (long)b * SEQL + s;
    const long base = m * (3 * HID) + (long)h * DHEAD + d;
    const long o = (long)bh * (SEQL * DHEAD) + (long)s * DHEAD + d;
    Qd[o] = f2tf32f(qkv[base]);
    Kd[o] = f2tf32f(qkv[base + HID]);
    Vtd[(long)bh * (SEQL * DHEAD) + (long)d * SEQL + s] = f2tf32f(qkv[base + 2 * HID]);
}

// ---------------- repack ctx[bh,s,d] -> ctxr[b*s, h*d] (rounded) ------------
__global__ void repack_ctx(const float* __restrict__ ctx, float* __restrict__ ctxr)
{
    const int t = blockIdx.x * 256 + threadIdx.x;
    const int hc = t & 2047;
    const int m  = t >> 11;
    const int d = hc & 127, h = hc >> 7;
    const int b = m >> 10, s = m & 1023;
    ctxr[t] = f2tf32f(
        ctx[((long)(b * NHEAD + h)) * (SEQL * DHEAD) + (long)s * DHEAD + d]);
}

// ---------------- weight rounding to tf32 -----------------------------------
__global__ void round_w(const float4* __restrict__ in, float4* __restrict__ out, int n4)
{
    int i = blockIdx.x * 256 + threadIdx.x;
    if (i < n4) {
        float4 v = in[i];
        v.x = f2tf32f(v.x); v.y = f2tf32f(v.y);
        v.z = f2tf32f(v.z); v.w = f2tf32f(v.w);
        out[i] = v;
    }
}

// ---------------- launch ----------------------------------------------------
extern "C" void kernel_launch(void* const* d_in, const int* in_sizes, int n_in,
                              void* d_out, int out_size)
{
    const float* x    = (const float*)d_in[0];
    const float* ln1w = (const float*)d_in[1];
    const float* ln1b = (const float*)d_in[2];
    const float* wqkv = (const float*)d_in[3];
    const float* wo   = (const float*)d_in[4];
    const float* ln2w = (const float*)d_in[5];
    const float* ln2b = (const float*)d_in[6];
    const float* w1   = (const float*)d_in[7];
    const float* b1   = (const float*)d_in[8];
    const float* w2   = (const float*)d_in[9];
    const float* b2   = (const float*)d_in[10];
    float* out = (float*)d_out;

    // GELU_RMS via the same quadrature as the reference
    double ssum = 0.0;
    const double dx = 24.0 / 48000.0;
    for (int i = 0; i <= 48000; i++) {
        double xx  = -12.0 + dx * i;
        double pdf = exp(-0.5 * xx * xx) / sqrt(2.0 * M_PI);
        double cdf = 0.5 * (1.0 + erf(xx / sqrt(2.0)));
        double gg  = xx * cdf;
        ssum += gg * gg * pdf;
    }
    const float inv_rms = (float)(1.0 / sqrt(ssum * dx));

    float* base;
    cudaGetSymbolAddress((void**)&base, g_scratch);
    float* py     = base + OFF_Y;
    float* pqkv   = base + OFF_QKV;
    float* pQ     = base + OFF_Q;
    float* pK     = base + OFF_K;
    float* pVt    = base + OFF_VT;
    float* pS     = base + OFF_S;
    float* pw1r   = base + OFF_W1R;
    float* pw2r   = base + OFF_W2R;
    float* pctx   = base + OFF_CTX;
    float* pctxr  = base + OFF_CTXR;
    float* px2    = base + OFF_X2;
    float* pmlp   = base + OFF_MLP;
    float* pwqkvr = base + OFF_WQKVR;
    float* pwor   = base + OFF_WOR;

    cudaFuncSetAttribute(gemm_tn<0>, cudaFuncAttributeMaxDynamicSharedMemorySize, GEMM_SMEM);
    cudaFuncSetAttribute(gemm_tn<1>, cudaFuncAttributeMaxDynamicSharedMemorySize, GEMM_SMEM);
    cudaFuncSetAttribute(gemm_tn<2>, cudaFuncAttributeMaxDynamicSharedMemorySize, GEMM_SMEM);
    cudaFuncSetAttribute(gemm_tn<3>, cudaFuncAttributeMaxDynamicSharedMemorySize, GEMM_SMEM);

    const float rs_h  = (float)(1.0 / sqrt((double)HID));
    const float rs_d  = (float)(1.0 / sqrt((double)DHEAD));
    const float a_ctx = (float)(32.0 / exp(0.5));
    const float a_o   = (float)(sqrt(0.01) / sqrt((double)HID));
    const float r_o   = (float)sqrt(0.99);
    const float a_w2  = (float)(sqrt(0.5) / sqrt((double)(4 * HID)));
    const float b_w2  = (float)sqrt(0.5);
    const float r_w2  = (float)sqrt(0.5);

    // 0. round wqkv/wo to tf32 (into mlp-region aliases; free until step 10)
    round_w<<<(3 * HID * HID / 4 + 255) / 256, 256>>>((const float4*)wqkv, (float4*)pwqkvr, 3 * HID * HID / 4);
    round_w<<<(HID * HID / 4 + 255) / 256, 256>>>((const float4*)wo, (float4*)pwor, HID * HID / 4);

    // 1. LN1 (tf32-rounded output)
    ln_kernel<<<MTOK, 256>>>(x, ln1w, ln1b, py);
    // 2. QKV = LN1(x) @ Wqkv^T * h^-0.5      [4096 x 6144]
    gemm_tn<0><<<dim3(48, 32, 1), 128, GEMM_SMEM>>>(
        py, pwqkvr, pqkv, MTOK, 3 * HID, HID, 0, 0, 0,
        rs_h, nullptr, 0.f, nullptr, 0.f, 0.f);
    // 3. pack Q/K/Vt (rounded)
    pack_qkv<<<32768, 256>>>(pqkv, pQ, pK, pVt);
    // 4. scores = Q K^T * d^-0.5             [64 x 1024 x 1024]
    gemm_tn<0><<<dim3(8, 8, BHTOT), 128, GEMM_SMEM>>>(
        pQ, pK, pS, SEQL, SEQL, DHEAD,
        (long)SEQL * DHEAD, (long)SEQL * DHEAD, (long)SEQL * SEQL,
        rs_d, nullptr, 0.f, nullptr, 0.f, 0.f);
    // 5. softmax (rounded probs)
    softmax_kernel<<<BHTOT * SEQL, 256>>>(pS);
    // 6. ctx = P @ V * sqrt(S)/sqrt(e)       [64 x 1024 x 128]
    gemm_tn<0><<<dim3(1, 8, BHTOT), 128, GEMM_SMEM>>>(
        pS, pVt, pctx, SEQL, DHEAD, SEQL,
        (long)SEQL * SEQL, (long)SEQL * DHEAD, (long)SEQL * DHEAD,
        a_ctx, nullptr, 0.f, nullptr, 0.f, 0.f);
    // 6.5 scores no longer needed: round w1/w2 into the S region
    round_w<<<(4 * HID * HID / 4 + 255) / 256, 256>>>((const float4*)w1, (float4*)pw1r, 4 * HID * HID / 4);
    round_w<<<(4 * HID * HID / 4 + 255) / 256, 256>>>((const float4*)w2, (float4*)pw2r, 4 * HID * HID / 4);
    // 7. repack ctx (rounded)
    repack_ctx<<<32768, 256>>>(pctx, pctxr);
    // 8. x2 = (ctx @ Wo^T)*h^-0.5*sqrt(tau) + x*sqrt(1-tau)
    gemm_tn<1><<<dim3(16, 32, 1), 128, GEMM_SMEM>>>(
        pctxr, pwor, px2, MTOK, HID, HID, 0, 0, 0,
        a_o, nullptr, 0.f, x, r_o, 0.f);
    // 9. LN2 (rounded output)
    ln_kernel<<<MTOK, 256>>>(px2, ln2w, ln2b, py);
    // 10. mlp = gelu_us( LN2 @ W1^T * h^-0.5 + b1 )
    gemm_tn<2><<<dim3(64, 32, 1), 128, GEMM_SMEM>>>(
        py, pw1r, pmlp, MTOK, 4 * HID, HID, 0, 0, 0,
        rs_h, b1, 1.0f, nullptr, 0.f, inv_rms);
    // 11. out = (mlp @ W2^T * (4h)^-0.5 + b2)*sqrt(.5) + x2*sqrt(.5)
    gemm_tn<3><<<dim3(16, 32, 1), 128, GEMM_SMEM>>>(
        pmlp, pw2r, out, MTOK, HID, 4 * HID, 0, 0, 0,
        a_w2, b2, b_w2, px2, r_w2, 0.f);
}

// round 9
// speedup vs baseline: 2.0264x; 1.9218x over previous
#include <cuda_runtime.h>
#include <cuda_fp16.h>
#include <cmath>
#include <cstdint>

// ---------------- problem constants ----------------
#define HID   2048
#define SEQL  1024
#define NBAT  4
#define NHEAD 16
#define DHEAD 128
#define MTOK  4096          // NBAT*SEQL
#define BHTOT 64            // NBAT*NHEAD

#define MB ((size_t)1048576)

// ---------------- single flat scratch: 624MB --------------------------------
// Byte offsets (MB):
//   Y     @0    (16)  fp16 LN output
//   QKV   @16   (48)  fp16
//   Q     @64   (16)  fp16 ; K @80 (16) ; VT @96 (16)
//   S     @112  (256) fp32 scores (steps 5-6); W1H @112 (32) + W2H @144 (32)
//                     fp16 weights, converted AFTER softmax (S dead)
//   P     @368  (128) fp16 probs
//   CTX   @496  (16)  fp16 ; CTXR @512 (16) fp16
//   X2    @528  (32)  fp32 residual
//   MLP   @560  (64)  fp16 (step 13+); hosts WQKVH @560 (24) + WOH @584 (8)
__device__ __align__(16) unsigned char g_scratch[624 * MB];

#define OFF_Y     (0 * MB)
#define OFF_QKV   (16 * MB)
#define OFF_Q     (64 * MB)
#define OFF_K     (80 * MB)
#define OFF_VT    (96 * MB)
#define OFF_S     (112 * MB)
#define OFF_W1H   (112 * MB)
#define OFF_W2H   (144 * MB)
#define OFF_P     (368 * MB)
#define OFF_CTX   (496 * MB)
#define OFF_CTXR  (512 * MB)
#define OFF_X2    (528 * MB)
#define OFF_MLP   (560 * MB)
#define OFF_WQKVH (560 * MB)
#define OFF_WOH   (584 * MB)

// ---------------- store helpers ---------------------------------------------
__device__ __forceinline__ void store2(float* C, long idx, float v0, float v1) {
    *(float2*)(C + idx) = make_float2(v0, v1);
}
__device__ __forceinline__ void store2(__half* C, long idx, float v0, float v1) {
    *(__half2*)(C + idx) = __floats2half2_rn(v0, v1);
}

// ---------------- GEMM: fp16 m16n8k16, 128x128 block, 8 warps, 64x32 tile ---
// C[m,n] = epilogue( alpha * sum_k A[m,k]*B[n,k] )  A: MxK fp16, B: NxK fp16
// BK=64, 2-stage cp.async, 2 CTAs/SM.
#define KP 72                              // halfs per smem row (64 + 8 pad)
#define STG_H ((128 + 128) * KP)           // 18432 halfs per stage
#define GEMM_SMEM (2 * STG_H * 2)          // 73728 B

// MODE 0: C = a*acc   1: +rscale*resid   2: gelu_us(a*acc+b) (->fp16)   3: a*acc+b+resid
template <int MODE, typename OUT_T>
__global__ void __launch_bounds__(256, 2)
gemm_tn(const __half* __restrict__ A, const __half* __restrict__ B,
        OUT_T* __restrict__ C,
        int M, int N, int K,
        long sA, long sB, long sC,
        float alpha,
        const float* __restrict__ bias, float bscale,
        const float* __restrict__ resid, float rscale,
        float inv_rms)
{
    extern __shared__ __half smh[];

    const int m0 = blockIdx.y * 128;
    const int n0 = blockIdx.x * 128;
    A += blockIdx.z * sA + (long)m0 * K;
    B += blockIdx.z * sB + (long)n0 * K;
    C += blockIdx.z * sC;
    const float* Rz = (MODE == 1 || MODE == 3) ? resid + blockIdx.z * sC : nullptr;

    const int tid  = threadIdx.x;
    const int lane = tid & 31;
    const int warp = tid >> 5;
    const int wm = warp >> 2;          // 0..1 (64 rows)
    const int wn = warp & 3;           // 0..3 (32 cols)
    const int g  = lane >> 2;          // 0..7
    const int t4 = lane & 3;           // 0..3

    float acc[4][4][4];
#pragma unroll
    for (int i = 0; i < 4; i++)
#pragma unroll
        for (int j = 0; j < 4; j++)
#pragma unroll
            for (int c = 0; c < 4; c++) acc[i][j][c] = 0.f;

    const int KT = K / 64;

    auto issue = [&](int kt, int buf) {
        __half* Sb = smh + buf * STG_H;
        const long kof = (long)kt * 64;
        // 2048 chunks of 16B (8 halfs): A rows [0,128) then B rows [0,128)
#pragma unroll
        for (int q = 0; q < 8; q++) {
            int idx = tid + q * 256;
            if (idx < 1024) {
                int r = idx >> 3, c = (idx & 7) * 8;
                unsigned d = (unsigned)__cvta_generic_to_shared(&Sb[r * KP + c]);
                asm volatile("cp.async.cg.shared.global [%0], [%1], 16;\n"
                             :: "r"(d), "l"(A + (long)r * K + kof + c) : "memory");
            } else {
                int j = idx - 1024;
                int r = j >> 3, c = (j & 7) * 8;
                unsigned d = (unsigned)__cvta_generic_to_shared(&Sb[(128 + r) * KP + c]);
                asm volatile("cp.async.cg.shared.global [%0], [%1], 16;\n"
                             :: "r"(d), "l"(B + (long)r * K + kof + c) : "memory");
            }
        }
        asm volatile("cp.async.commit_group;\n" ::: "memory");
    };

    issue(0, 0);

    for (int kt = 0; kt < KT; kt++) {
        const int buf = kt & 1;
        asm volatile("cp.async.wait_group 0;\n" ::: "memory");
        __syncthreads();   // stage kt visible; all warps done with buffer (kt+1)&1
        if (kt + 1 < KT) issue(kt + 1, buf ^ 1);

        const __half* Asb = smh + buf * STG_H;
        const __half* Bsb = Asb + 128 * KP;

#pragma unroll
        for (int ks = 0; ks < 4; ks++) {      // 4 x k16 steps = K 64
            const int kb = ks * 16;
            unsigned af[4][4], bf[4][2];
#pragma unroll
            for (int mt = 0; mt < 4; mt++) {
                int r = wm * 64 + mt * 16;
                af[mt][0] = *(const unsigned*)&Asb[(r + g    ) * KP + kb + t4 * 2];
                af[mt][1] = *(const unsigned*)&Asb[(r + g + 8) * KP + kb + t4 * 2];
                af[mt][2] = *(const unsigned*)&Asb[(r + g    ) * KP + kb + 8 + t4 * 2];
                af[mt][3] = *(const unsigned*)&Asb[(r + g + 8) * KP + kb + 8 + t4 * 2];
            }
#pragma unroll
            for (int nt = 0; nt < 4; nt++) {
                int c = wn * 32 + nt * 8;
                bf[nt][0] = *(const unsigned*)&Bsb[(c + g) * KP + kb + t4 * 2];
                bf[nt][1] = *(const unsigned*)&Bsb[(c + g) * KP + kb + 8 + t4 * 2];
            }
#pragma unroll
            for (int mt = 0; mt < 4; mt++)
#pragma unroll
                for (int nt = 0; nt < 4; nt++) {
                    asm volatile(
                        "mma.sync.aligned.m16n8k16.row.col.f32.f16.f16.f32 "
                        "{%0,%1,%2,%3}, {%4,%5,%6,%7}, {%8,%9}, {%0,%1,%2,%3};\n"
                        : "+f"(acc[mt][nt][0]), "+f"(acc[mt][nt][1]),
                          "+f"(acc[mt][nt][2]), "+f"(acc[mt][nt][3])
                        : "r"(af[mt][0]), "r"(af[mt][1]), "r"(af[mt][2]), "r"(af[mt][3]),
                          "r"(bf[nt][0]), "r"(bf[nt][1]));
                }
        }
    }

    // ---------------- epilogue ----------------
#pragma unroll
    for (int mt = 0; mt < 4; mt++) {
        int rbase = m0 + wm * 64 + mt * 16;
#pragma unroll
        for (int nt = 0; nt < 4; nt++) {
            int c0 = n0 + wn * 32 + nt * 8 + 2 * t4;
#pragma unroll
            for (int half_i = 0; half_i < 2; half_i++) {
                int r = rbase + g + half_i * 8;
                float v0 = acc[mt][nt][half_i * 2 + 0] * alpha;
                float v1 = acc[mt][nt][half_i * 2 + 1] * alpha;
                if (MODE == 2 || MODE == 3) {
                    v0 += bias[c0] * bscale;
                    v1 += bias[c0 + 1] * bscale;
                }
                if (MODE == 2) {
                    v0 = v0 * normcdff(v0) * inv_rms;
                    v1 = v1 * normcdff(v1) * inv_rms;
                }
                long idx = (long)r * N + c0;
                if (MODE == 1 || MODE == 3) {
                    float2 rv = *(const float2*)(Rz + idx);
                    v0 += rv.x * rscale;
                    v1 += rv.y * rscale;
                }
                store2(C, idx, v0, v1);
            }
        }
    }
}

// ---------------- LayerNorm (fp32 in -> fp16 out) ---------------------------
__global__ void ln_kernel(const float* __restrict__ xin,
                          const float* __restrict__ w,
                          const float* __restrict__ b,
                          __half* __restrict__ y)
{
    __shared__ float red[16];
    const long row = blockIdx.x;
    const float4* xr = (const float4*)(xin + row * HID);
    const int t = threadIdx.x;

    float4 v0 = xr[t];
    float4 v1 = xr[t + 256];
    float s  = v0.x + v0.y + v0.z + v0.w + v1.x + v1.y + v1.z + v1.w;
    float sq = v0.x*v0.x + v0.y*v0.y + v0.z*v0.z + v0.w*v0.w
             + v1.x*v1.x + v1.y*v1.y + v1.z*v1.z + v1.w*v1.w;
#pragma unroll
    for (int o = 16; o; o >>= 1) {
        s  += __shfl_xor_sync(0xffffffffu, s,  o);
        sq += __shfl_xor_sync(0xffffffffu, sq, o);
    }
    if ((t & 31) == 0) { red[t >> 5] = s; red[8 + (t >> 5)] = sq; }
    __syncthreads();
    if (t == 0) {
        float S = 0.f, Q = 0.f;
        for (int i = 0; i < 8; i++) { S += red[i]; Q += red[8 + i]; }
        red[0] = S; red[8] = Q;
    }
    __syncthreads();
    const float mean = red[0] * (1.0f / HID);
    float var = red[8] * (1.0f / HID) - mean * mean;
    var = fmaxf(var, 0.0f);
    const float rstd = rsqrtf(var + 1e-5f);

    __half2* yh = (__half2*)(y + row * HID);
    const float4 w0 = ((const float4*)w)[t];
    const float4 w1 = ((const float4*)w)[t + 256];
    const float4 b0 = ((const float4*)b)[t];
    const float4 b1 = ((const float4*)b)[t + 256];
    yh[2 * t]           = __floats2half2_rn((v0.x - mean) * rstd * w0.x + b0.x,
                                            (v0.y - mean) * rstd * w0.y + b0.y);
    yh[2 * t + 1]       = __floats2half2_rn((v0.z - mean) * rstd * w0.z + b0.z,
                                            (v0.w - mean) * rstd * w0.w + b0.w);
    yh[512 + 2 * t]     = __floats2half2_rn((v1.x - mean) * rstd * w1.x + b1.x,
                                            (v1.y - mean) * rstd * w1.y + b1.y);
    yh[512 + 2 * t + 1] = __floats2half2_rn((v1.z - mean) * rstd * w1.z + b1.z,
                                            (v1.w - mean) * rstd * w1.w + b1.w);
}

// ---------------- softmax: fp32 scores -> fp16 probs ------------------------
__global__ void softmax_kernel(const float* __restrict__ S, __half* __restrict__ P)
{
    __shared__ float red[16];
    const size_t row = blockIdx.x;
    const float4* p = (const float4*)(S + row * (size_t)SEQL);
    const int t = threadIdx.x;

    float4 v = p[t];
    float mx = fmaxf(fmaxf(v.x, v.y), fmaxf(v.z, v.w));
#pragma unroll
    for (int o = 16; o; o >>= 1) mx = fmaxf(mx, __shfl_xor_sync(0xffffffffu, mx, o));
    if ((t & 31) == 0) red[t >> 5] = mx;
    __syncthreads();
    if (t == 0) {
        float m = red[0];
        for (int i = 1; i < 8; i++) m = fmaxf(m, red[i]);
        red[0] = m;
    }
    __syncthreads();
    mx = red[0];

    float e0 = expf(v.x - mx), e1 = expf(v.y - mx);
    float e2 = expf(v.z - mx), e3 = expf(v.w - mx);
    float s = e0 + e1 + e2 + e3;
#pragma unroll
    for (int o = 16; o; o >>= 1) s += __shfl_xor_sync(0xffffffffu, s, o);
    if ((t & 31) == 0) red[8 + (t >> 5)] = s;
    __syncthreads();
    if (t == 0) {
        float S2 = 0.f;
        for (int i = 0; i < 8; i++) S2 += red[8 + i];
        red[8] = S2;
    }
    __syncthreads();
    const float inv = 1.0f / red[8];

    __half2* ph = (__half2*)(P + row * (size_t)SEQL);
    ph[2 * t]     = __floats2half2_rn(e0 * inv, e1 * inv);
    ph[2 * t + 1] = __floats2half2_rn(e2 * inv, e3 * inv);
}

// ---------------- pack qkv(fp16) -> Q[bh,s,d], K[bh,s,d], Vt[bh,d,s] --------
__global__ void pack_qkv(const __half* __restrict__ qkv,
                         __half* __restrict__ Qd, __half* __restrict__ Kd,
                         __half* __restrict__ Vtd)
{
    const int t = blockIdx.x * 256 + threadIdx.x;
    const int d  = t & 127;
    const int s  = (t >> 7) & 1023;
    const int bh = t >> 17;
    const int b  = bh >> 4, h = bh & 15;
    const long m = (long)b * SEQL + s;
    const long base = m * (3 * HID) + (long)h * DHEAD + d;
    const long o = (long)bh * (SEQL * DHEAD) + (long)s * DHEAD + d;
    Qd[o] = qkv[base];
    Kd[o] = qkv[base + HID];
    Vtd[(long)bh * (SEQL * DHEAD) + (long)d * SEQL + s] = qkv[base + 2 * HID];
}

// ---------------- repack ctx[bh,s,d] -> ctxr[b*s, h*d] (fp16) ---------------
__global__ void repack_ctx(const __half* __restrict__ ctx, __half* __restrict__ ctxr)
{
    const int t = blockIdx.x * 256 + threadIdx.x;
    const int hc = t & 2047;
    const int m  = t >> 11;
    const int d = hc & 127, h = hc >> 7;
    const int b = m >> 10, s = m & 1023;
    ctxr[t] = ctx[((long)(b * NHEAD + h)) * (SEQL * DHEAD) + (long)s * DHEAD + d];
}

// ---------------- weight conversion fp32 -> fp16 ----------------------------
__global__ void cvt_w(const float4* __restrict__ in, __half* __restrict__ out, int n4)
{
    int i = blockIdx.x * 256 + threadIdx.x;
    if (i < n4) {
        float4 v = in[i];
        __half2* o = (__half2*)(out + (size_t)i * 4);
        o[0] = __floats2half2_rn(v.x, v.y);
        o[1] = __floats2half2_rn(v.z, v.w);
    }
}

// ---------------- launch ----------------------------------------------------
extern "C" void kernel_launch(void* const* d_in, const int* in_sizes, int n_in,
                              void* d_out, int out_size)
{
    const float* x    = (const float*)d_in[0];
    const float* ln1w = (const float*)d_in[1];
    const float* ln1b = (const float*)d_in[2];
    const float* wqkv = (const float*)d_in[3];
    const float* wo   = (const float*)d_in[4];
    const float* ln2w = (const float*)d_in[5];
    const float* ln2b = (const float*)d_in[6];
    const float* w1   = (const float*)d_in[7];
    const float* b1   = (const float*)d_in[8];
    const float* w2   = (const float*)d_in[9];
    const float* b2   = (const float*)d_in[10];
    float* out = (float*)d_out;

    // GELU_RMS via the same quadrature as the reference
    double ssum = 0.0;
    const double dx = 24.0 / 48000.0;
    for (int i = 0; i <= 48000; i++) {
        double xx  = -12.0 + dx * i;
        double pdf = exp(-0.5 * xx * xx) / sqrt(2.0 * M_PI);
        double cdf = 0.5 * (1.0 + erf(xx / sqrt(2.0)));
        double gg  = xx * cdf;
        ssum += gg * gg * pdf;
    }
    const float inv_rms = (float)(1.0 / sqrt(ssum * dx));

    unsigned char* base;
    cudaGetSymbolAddress((void**)&base, g_scratch);
    __half* pY     = (__half*)(base + OFF_Y);
    __half* pQKV   = (__half*)(base + OFF_QKV);
    __half* pQ     = (__half*)(base + OFF_Q);
    __half* pK     = (__half*)(base + OFF_K);
    __half* pVT    = (__half*)(base + OFF_VT);
    float*  pS     = (float*) (base + OFF_S);
    __half* pW1H   = (__half*)(base + OFF_W1H);
    __half* pW2H   = (__half*)(base + OFF_W2H);
    __half* pP     = (__half*)(base + OFF_P);
    __half* pCTX   = (__half*)(base + OFF_CTX);
    __half* pCTXR  = (__half*)(base + OFF_CTXR);
    float*  pX2    = (float*) (base + OFF_X2);
    __half* pMLP   = (__half*)(base + OFF_MLP);
    __half* pWQKVH = (__half*)(base + OFF_WQKVH);
    __half* pWOH   = (__half*)(base + OFF_WOH);

    cudaFuncSetAttribute(gemm_tn<0, __half>, cudaFuncAttributeMaxDynamicSharedMemorySize, GEMM_SMEM);
    cudaFuncSetAttribute(gemm_tn<0, float>,  cudaFuncAttributeMaxDynamicSharedMemorySize, GEMM_SMEM);
    cudaFuncSetAttribute(gemm_tn<1, float>,  cudaFuncAttributeMaxDynamicSharedMemorySize, GEMM_SMEM);
    cudaFuncSetAttribute(gemm_tn<2, __half>, cudaFuncAttributeMaxDynamicSharedMemorySize, GEMM_SMEM);
    cudaFuncSetAttribute(gemm_tn<3, float>,  cudaFuncAttributeMaxDynamicSharedMemorySize, GEMM_SMEM);

    const float rs_h  = (float)(1.0 / sqrt((double)HID));
    const float rs_d  = (float)(1.0 / sqrt((double)DHEAD));
    const float a_ctx = (float)(32.0 / exp(0.5));
    const float a_o   = (float)(sqrt(0.01) / sqrt((double)HID));
    const float r_o   = (float)sqrt(0.99);
    const float a_w2  = (float)(sqrt(0.5) / sqrt((double)(4 * HID)));
    const float b_w2  = (float)sqrt(0.5);
    const float r_w2  = (float)sqrt(0.5);

    // 0. convert wqkv/wo to fp16 (into mlp-region aliases; dead before step 13)
    cvt_w<<<(3 * HID * HID / 4 + 255) / 256, 256>>>((const float4*)wqkv, pWQKVH, 3 * HID * HID / 4);
    cvt_w<<<(HID * HID / 4 + 255) / 256, 256>>>((const float4*)wo, pWOH, HID * HID / 4);

    // 1. LN1 -> fp16
    ln_kernel<<<MTOK, 256>>>(x, ln1w, ln1b, pY);
    // 2. QKV = LN1(x) @ Wqkv^T * h^-0.5      [4096 x 6144] -> fp16
    gemm_tn<0, __half><<<dim3(48, 32, 1), 256, GEMM_SMEM>>>(
        pY, pWQKVH, pQKV, MTOK, 3 * HID, HID, 0, 0, 0,
        rs_h, nullptr, 0.f, nullptr, 0.f, 0.f);
    // 3. pack Q/K/Vt (fp16)
    pack_qkv<<<32768, 256>>>(pQKV, pQ, pK, pVT);
    // 4. scores = Q K^T * d^-0.5             [64 x 1024 x 1024] -> fp32
    gemm_tn<0, float><<<dim3(8, 8, BHTOT), 256, GEMM_SMEM>>>(
        pQ, pK, pS, SEQL, SEQL, DHEAD,
        (long)SEQL * DHEAD, (long)SEQL * DHEAD, (long)SEQL * SEQL,
        rs_d, nullptr, 0.f, nullptr, 0.f, 0.f);
    // 5. softmax: S(fp32) -> P(fp16)
    softmax_kernel<<<BHTOT * SEQL, 256>>>(pS, pP);
    // 5.5 S dead: convert w1/w2 (fp16) into the S region
    cvt_w<<<(4 * HID * HID / 4 + 255) / 256, 256>>>((const float4*)w1, pW1H, 4 * HID * HID / 4);
    cvt_w<<<(4 * HID * HID / 4 + 255) / 256, 256>>>((const float4*)w2, pW2H, 4 * HID * HID / 4);
    // 6. ctx = P @ V * sqrt(S)/sqrt(e)       [64 x 1024 x 128] -> fp16
    gemm_tn<0, __half><<<dim3(1, 8, BHTOT), 256, GEMM_SMEM>>>(
        pP, pVT, pCTX, SEQL, DHEAD, SEQL,
        (long)SEQL * SEQL, (long)SEQL * DHEAD, (long)SEQL * DHEAD,
        a_ctx, nullptr, 0.f, nullptr, 0.f, 0.f);
    // 7. repack ctx (fp16)
    repack_ctx<<<32768, 256>>>(pCTX, pCTXR);
    // 8. x2 = (ctx @ Wo^T)*h^-0.5*sqrt(tau) + x*sqrt(1-tau)  -> fp32
    gemm_tn<1, float><<<dim3(16, 32, 1), 256, GEMM_SMEM>>>(
        pCTXR, pWOH, pX2, MTOK, HID, HID, 0, 0, 0,
        a_o, nullptr, 0.f, x, r_o, 0.f);
    // 9. LN2 -> fp16
    ln_kernel<<<MTOK, 256>>>(pX2, ln2w, ln2b, pY);
    // 10. mlp = gelu_us( LN2 @ W1^T * h^-0.5 + b1 )  -> fp16
    gemm_tn<2, __half><<<dim3(64, 32, 1), 256, GEMM_SMEM>>>(
        pY, pW1H, pMLP, MTOK, 4 * HID, HID, 0, 0, 0,
        rs_h, b1, 1.0f, nullptr, 0.f, inv_rms);
    // 11. out = (mlp @ W2^T * (4h)^-0.5 + b2)*sqrt(.5) + x2*sqrt(.5)  -> fp32
    gemm_tn<3, float><<<dim3(16, 32, 1), 256, GEMM_SMEM>>>(
        pMLP, pW2H, out, MTOK, HID, 4 * HID, 0, 0, 0,
        a_w2, b2, b_w2, pX2, r_w2, 0.f);
}

// round 10
// speedup vs baseline: 2.2134x; 1.0923x over previous
#include <cuda_runtime.h>
#include <cuda_fp16.h>
#include <cmath>
#include <cstdint>

// ---------------- problem constants ----------------
#define HID   2048
#define SEQL  1024
#define NBAT  4
#define NHEAD 16
#define DHEAD 128
#define MTOK  4096          // NBAT*SEQL
#define BHTOT 64            // NBAT*NHEAD

#define MB ((size_t)1048576)

// ---------------- single flat scratch: 624MB --------------------------------
__device__ __align__(16) unsigned char g_scratch[624 * MB];

#define OFF_Y     (0 * MB)
#define OFF_QKV   (16 * MB)
#define OFF_Q     (64 * MB)
#define OFF_K     (80 * MB)
#define OFF_VT    (96 * MB)
#define OFF_S     (112 * MB)
#define OFF_W1H   (112 * MB)
#define OFF_W2H   (144 * MB)
#define OFF_P     (368 * MB)
#define OFF_CTX   (496 * MB)
#define OFF_CTXR  (512 * MB)
#define OFF_X2    (528 * MB)
#define OFF_MLP   (560 * MB)
#define OFF_WQKVH (560 * MB)
#define OFF_WOH   (584 * MB)

// ---------------- store helpers ---------------------------------------------
__device__ __forceinline__ void store2(float* C, long idx, float v0, float v1) {
    *(float2*)(C + idx) = make_float2(v0, v1);
}
__device__ __forceinline__ void store2(__half* C, long idx, float v0, float v1) {
    *(__half2*)(C + idx) = __floats2half2_rn(v0, v1);
}

__device__ __forceinline__ void ldsm4(unsigned* r, uint32_t a) {
    asm volatile("ldmatrix.sync.aligned.m8n8.x4.shared.b16 {%0,%1,%2,%3}, [%4];"
                 : "=r"(r[0]), "=r"(r[1]), "=r"(r[2]), "=r"(r[3]) : "r"(a));
}

// ---------------- GEMM: fp16 m16n8k16, 128x128 block, 8 warps, 64x32 tile ---
// C[m,n] = epilogue( alpha * sum_k A[m,k]*B[n,k] )  A: MxK fp16, B: NxK fp16
// BK=64, 2-stage cp.async, 2 CTAs/SM, ldmatrix fragment loads.
#define KP 72                              // halfs per smem row (64 + 8 pad)
#define STG_H ((128 + 128) * KP)           // 18432 halfs per stage
#define GEMM_SMEM (2 * STG_H * 2)          // 73728 B

// MODE 0: C = a*acc   1: +rscale*resid   2: gelu_us(a*acc+b) (->fp16)   3: a*acc+b+resid
template <int MODE, typename OUT_T>
__global__ void __launch_bounds__(256, 2)
gemm_tn(const __half* __restrict__ A, const __half* __restrict__ B,
        OUT_T* __restrict__ C,
        int M, int N, int K,
        long sA, long sB, long sC,
        float alpha,
        const float* __restrict__ bias, float bscale,
        const float* __restrict__ resid, float rscale,
        float inv_rms)
{
    extern __shared__ __half smh[];

    const int m0 = blockIdx.y * 128;
    const int n0 = blockIdx.x * 128;
    A += blockIdx.z * sA + (long)m0 * K;
    B += blockIdx.z * sB + (long)n0 * K;
    C += blockIdx.z * sC;
    const float* Rz = (MODE == 1 || MODE == 3) ? resid + blockIdx.z * sC : nullptr;

    const int tid  = threadIdx.x;
    const int lane = tid & 31;
    const int warp = tid >> 5;
    const int wm = warp >> 2;          // 0..1 (64 rows)
    const int wn = warp & 3;           // 0..3 (32 cols)
    const int g  = lane >> 2;          // 0..7
    const int t4 = lane & 3;           // 0..3

    // ldmatrix per-lane source rows/cols
    // A x4: tiles (r,kb),(r+8,kb),(r,kb+8),(r+8,kb+8)
    const int a_row = wm * 64 + (lane & 7) + ((lane >> 3) & 1) * 8;
    const int a_col = (lane >> 4) * 8;
    // B x4 (two nt at once): tiles (c,kb),(c,kb+8),(c+8,kb),(c+8,kb+8)
    const int b_row = wn * 32 + (lane & 7) + ((lane >> 4) & 1) * 8;
    const int b_col = ((lane >> 3) & 1) * 8;

    const uint32_t smbase = (uint32_t)__cvta_generic_to_shared(smh);

    float acc[4][4][4];
#pragma unroll
    for (int i = 0; i < 4; i++)
#pragma unroll
        for (int j = 0; j < 4; j++)
#pragma unroll
            for (int c = 0; c < 4; c++) acc[i][j][c] = 0.f;

    const int KT = K / 64;

    auto issue = [&](int kt, int buf) {
        __half* Sb = smh + buf * STG_H;
        const long kof = (long)kt * 64;
#pragma unroll
        for (int q = 0; q < 8; q++) {
            int idx = tid + q * 256;
            if (idx < 1024) {
                int r = idx >> 3, c = (idx & 7) * 8;
                unsigned d = (unsigned)__cvta_generic_to_shared(&Sb[r * KP + c]);
                asm volatile("cp.async.cg.shared.global [%0], [%1], 16;\n"
                             :: "r"(d), "l"(A + (long)r * K + kof + c) : "memory");
            } else {
                int j = idx - 1024;
                int r = j >> 3, c = (j & 7) * 8;
                unsigned d = (unsigned)__cvta_generic_to_shared(&Sb[(128 + r) * KP + c]);
                asm volatile("cp.async.cg.shared.global [%0], [%1], 16;\n"
                             :: "r"(d), "l"(B + (long)r * K + kof + c) : "memory");
            }
        }
        asm volatile("cp.async.commit_group;\n" ::: "memory");
    };

    issue(0, 0);

    for (int kt = 0; kt < KT; kt++) {
        const int buf = kt & 1;
        asm volatile("cp.async.wait_group 0;\n" ::: "memory");
        __syncthreads();
        if (kt + 1 < KT) issue(kt + 1, buf ^ 1);

        const uint32_t abase = smbase + buf * (STG_H * 2);
        const uint32_t bbase = abase + 128 * KP * 2;

#pragma unroll
        for (int ks = 0; ks < 4; ks++) {      // 4 x k16 steps = K 64
            const int kb = ks * 16;
            unsigned af[4][4], bf[4][2];
#pragma unroll
            for (int mt = 0; mt < 4; mt++)
                ldsm4(af[mt], abase + ((a_row + mt * 16) * KP + kb + a_col) * 2);
#pragma unroll
            for (int p = 0; p < 2; p++) {
                unsigned t[4];
                ldsm4(t, bbase + ((b_row + p * 16) * KP + kb + b_col) * 2);
                bf[2 * p][0] = t[0]; bf[2 * p][1] = t[1];
                bf[2 * p + 1][0] = t[2]; bf[2 * p + 1][1] = t[3];
            }
#pragma unroll
            for (int mt = 0; mt < 4; mt++)
#pragma unroll
                for (int nt = 0; nt < 4; nt++) {
                    asm volatile(
                        "mma.sync.aligned.m16n8k16.row.col.f32.f16.f16.f32 "
                        "{%0,%1,%2,%3}, {%4,%5,%6,%7}, {%8,%9}, {%0,%1,%2,%3};\n"
                        : "+f"(acc[mt][nt][0]), "+f"(acc[mt][nt][1]),
                          "+f"(acc[mt][nt][2]), "+f"(acc[mt][nt][3])
                        : "r"(af[mt][0]), "r"(af[mt][1]), "r"(af[mt][2]), "r"(af[mt][3]),
                          "r"(bf[nt][0]), "r"(bf[nt][1]));
                }
        }
    }

    // ---------------- epilogue ----------------
#pragma unroll
    for (int mt = 0; mt < 4; mt++) {
        int rbase = m0 + wm * 64 + mt * 16;
#pragma unroll
        for (int nt = 0; nt < 4; nt++) {
            int c0 = n0 + wn * 32 + nt * 8 + 2 * t4;
#pragma unroll
            for (int half_i = 0; half_i < 2; half_i++) {
                int r = rbase + g + half_i * 8;
                float v0 = acc[mt][nt][half_i * 2 + 0] * alpha;
                float v1 = acc[mt][nt][half_i * 2 + 1] * alpha;
                if (MODE == 2 || MODE == 3) {
                    v0 += bias[c0] * bscale;
                    v1 += bias[c0 + 1] * bscale;
                }
                if (MODE == 2) {
                    v0 = v0 * normcdff(v0) * inv_rms;
                    v1 = v1 * normcdff(v1) * inv_rms;
                }
                long idx = (long)r * N + c0;
                if (MODE == 1 || MODE == 3) {
                    float2 rv = *(const float2*)(Rz + idx);
                    v0 += rv.x * rscale;
                    v1 += rv.y * rscale;
                }
                store2(C, idx, v0, v1);
            }
        }
    }
}

// ---------------- LayerNorm (fp32 in -> fp16 out) ---------------------------
__global__ void ln_kernel(const float* __restrict__ xin,
                          const float* __restrict__ w,
                          const float* __restrict__ b,
                          __half* __restrict__ y)
{
    __shared__ float red[16];
    const long row = blockIdx.x;
    const float4* xr = (const float4*)(xin + row * HID);
    const int t = threadIdx.x;

    float4 v0 = xr[t];
    float4 v1 = xr[t + 256];
    float s  = v0.x + v0.y + v0.z + v0.w + v1.x + v1.y + v1.z + v1.w;
    float sq = v0.x*v0.x + v0.y*v0.y + v0.z*v0.z + v0.w*v0.w
             + v1.x*v1.x + v1.y*v1.y + v1.z*v1.z + v1.w*v1.w;
#pragma unroll
    for (int o = 16; o; o >>= 1) {
        s  += __shfl_xor_sync(0xffffffffu, s,  o);
        sq += __shfl_xor_sync(0xffffffffu, sq, o);
    }
    if ((t & 31) == 0) { red[t >> 5] = s; red[8 + (t >> 5)] = sq; }
    __syncthreads();
    if (t == 0) {
        float S = 0.f, Q = 0.f;
        for (int i = 0; i < 8; i++) { S += red[i]; Q += red[8 + i]; }
        red[0] = S; red[8] = Q;
    }
    __syncthreads();
    const float mean = red[0] * (1.0f / HID);
    float var = red[8] * (1.0f / HID) - mean * mean;
    var = fmaxf(var, 0.0f);
    const float rstd = rsqrtf(var + 1e-5f);

    __half2* yh = (__half2*)(y + row * HID);
    const float4 w0 = ((const float4*)w)[t];
    const float4 w1 = ((const float4*)w)[t + 256];
    const float4 b0 = ((const float4*)b)[t];
    const float4 b1 = ((const float4*)b)[t + 256];
    yh[2 * t]           = __floats2half2_rn((v0.x - mean) * rstd * w0.x + b0.x,
                                            (v0.y - mean) * rstd * w0.y + b0.y);
    yh[2 * t + 1]       = __floats2half2_rn((v0.z - mean) * rstd * w0.z + b0.z,
                                            (v0.w - mean) * rstd * w0.w + b0.w);
    yh[512 + 2 * t]     = __floats2half2_rn((v1.x - mean) * rstd * w1.x + b1.x,
                                            (v1.y - mean) * rstd * w1.y + b1.y);
    yh[512 + 2 * t + 1] = __floats2half2_rn((v1.z - mean) * rstd * w1.z + b1.z,
                                            (v1.w - mean) * rstd * w1.w + b1.w);
}

// ---------------- softmax: fp32 scores -> fp16 probs ------------------------
__global__ void softmax_kernel(const float* __restrict__ S, __half* __restrict__ P)
{
    __shared__ float red[16];
    const size_t row = blockIdx.x;
    const float4* p = (const float4*)(S + row * (size_t)SEQL);
    const int t = threadIdx.x;

    float4 v = p[t];
    float mx = fmaxf(fmaxf(v.x, v.y), fmaxf(v.z, v.w));
#pragma unroll
    for (int o = 16; o; o >>= 1) mx = fmaxf(mx, __shfl_xor_sync(0xffffffffu, mx, o));
    if ((t & 31) == 0) red[t >> 5] = mx;
    __syncthreads();
    if (t == 0) {
        float m = red[0];
        for (int i = 1; i < 8; i++) m = fmaxf(m, red[i]);
        red[0] = m;
    }
    __syncthreads();
    mx = red[0];

    float e0 = expf(v.x - mx), e1 = expf(v.y - mx);
    float e2 = expf(v.z - mx), e3 = expf(v.w - mx);
    float s = e0 + e1 + e2 + e3;
#pragma unroll
    for (int o = 16; o; o >>= 1) s += __shfl_xor_sync(0xffffffffu, s, o);
    if ((t & 31) == 0) red[8 + (t >> 5)] = s;
    __syncthreads();
    if (t == 0) {
        float S2 = 0.f;
        for (int i = 0; i < 8; i++) S2 += red[8 + i];
        red[8] = S2;
    }
    __syncthreads();
    const float inv = 1.0f / red[8];

    __half2* ph = (__half2*)(P + row * (size_t)SEQL);
    ph[2 * t]     = __floats2half2_rn(e0 * inv, e1 * inv);
    ph[2 * t + 1] = __floats2half2_rn(e2 * inv, e3 * inv);
}

// ---------------- pack qkv(fp16) -> Q[bh,s,d], K[bh,s,d], Vt[bh,d,s] --------
__global__ void pack_qkv(const __half* __restrict__ qkv,
                         __half* __restrict__ Qd, __half* __restrict__ Kd,
                         __half* __restrict__ Vtd)
{
    const int t = blockIdx.x * 256 + threadIdx.x;
    const int d  = t & 127;
    const int s  = (t >> 7) & 1023;
    const int bh = t >> 17;
    const int b  = bh >> 4, h = bh & 15;
    const long m = (long)b * SEQL + s;
    const long base = m * (3 * HID) + (long)h * DHEAD + d;
    const long o = (long)bh * (SEQL * DHEAD) + (long)s * DHEAD + d;
    Qd[o] = qkv[base];
    Kd[o] = qkv[base + HID];
    Vtd[(long)bh * (SEQL * DHEAD) + (long)d * SEQL + s] = qkv[base + 2 * HID];
}

// ---------------- repack ctx[bh,s,d] -> ctxr[b*s, h*d] (fp16) ---------------
__global__ void repack_ctx(const __half* __restrict__ ctx, __half* __restrict__ ctxr)
{
    const int t = blockIdx.x * 256 + threadIdx.x;
    const int hc = t & 2047;
    const int m  = t >> 11;
    const int d = hc & 127, h = hc >> 7;
    const int b = m >> 10, s = m & 1023;
    ctxr[t] = ctx[((long)(b * NHEAD + h)) * (SEQL * DHEAD) + (long)s * DHEAD + d];
}

// ---------------- weight conversion fp32 -> fp16 ----------------------------
__global__ void cvt_w(const float4* __restrict__ in, __half* __restrict__ out, int n4)
{
    int i = blockIdx.x * 256 + threadIdx.x;
    if (i < n4) {
        float4 v = in[i];
        __half2* o = (__half2*)(out + (size_t)i * 4);
        o[0] = __floats2half2_rn(v.x, v.y);
        o[1] = __floats2half2_rn(v.z, v.w);
    }
}

// ---------------- launch ----------------------------------------------------
extern "C" void kernel_launch(void* const* d_in, const int* in_sizes, int n_in,
                              void* d_out, int out_size)
{
    const float* x    = (const float*)d_in[0];
    const float* ln1w = (const float*)d_in[1];
    const float* ln1b = (const float*)d_in[2];
    const float* wqkv = (const float*)d_in[3];
    const float* wo   = (const float*)d_in[4];
    const float* ln2w = (const float*)d_in[5];
    const float* ln2b = (const float*)d_in[6];
    const float* w1   = (const float*)d_in[7];
    const float* b1   = (const float*)d_in[8];
    const float* w2   = (const float*)d_in[9];
    const float* b2   = (const float*)d_in[10];
    float* out = (float*)d_out;

    // GELU_RMS via the same quadrature as the reference
    double ssum = 0.0;
    const double dx = 24.0 / 48000.0;
    for (int i = 0; i <= 48000; i++) {
        double xx  = -12.0 + dx * i;
        double pdf = exp(-0.5 * xx * xx) / sqrt(2.0 * M_PI);
        double cdf = 0.5 * (1.0 + erf(xx / sqrt(2.0)));
        double gg  = xx * cdf;
        ssum += gg * gg * pdf;
    }
    const float inv_rms = (float)(1.0 / sqrt(ssum * dx));

    unsigned char* base;
    cudaGetSymbolAddress((void**)&base, g_scratch);
    __half* pY     = (__half*)(base + OFF_Y);
    __half* pQKV   = (__half*)(base + OFF_QKV);
    __half* pQ     = (__half*)(base + OFF_Q);
    __half* pK     = (__half*)(base + OFF_K);
    __half* pVT    = (__half*)(base + OFF_VT);
    float*  pS     = (float*) (base + OFF_S);
    __half* pW1H   = (__half*)(base + OFF_W1H);
    __half* pW2H   = (__half*)(base + OFF_W2H);
    __half* pP     = (__half*)(base + OFF_P);
    __half* pCTX   = (__half*)(base + OFF_CTX);
    __half* pCTXR  = (__half*)(base + OFF_CTXR);
    float*  pX2    = (float*) (base + OFF_X2);
    __half* pMLP   = (__half*)(base + OFF_MLP);
    __half* pWQKVH = (__half*)(base + OFF_WQKVH);
    __half* pWOH   = (__half*)(base + OFF_WOH);

    cudaFuncSetAttribute(gemm_tn<0, __half>, cudaFuncAttributeMaxDynamicSharedMemorySize, GEMM_SMEM);
    cudaFuncSetAttribute(gemm_tn<0, float>,  cudaFuncAttributeMaxDynamicSharedMemorySize, GEMM_SMEM);
    cudaFuncSetAttribute(gemm_tn<1, float>,  cudaFuncAttributeMaxDynamicSharedMemorySize, GEMM_SMEM);
    cudaFuncSetAttribute(gemm_tn<2, __half>, cudaFuncAttributeMaxDynamicSharedMemorySize, GEMM_SMEM);
    cudaFuncSetAttribute(gemm_tn<3, float>,  cudaFuncAttributeMaxDynamicSharedMemorySize, GEMM_SMEM);

    const float rs_h  = (float)(1.0 / sqrt((double)HID));
    const float rs_d  = (float)(1.0 / sqrt((double)DHEAD));
    const float a_ctx = (float)(32.0 / exp(0.5));
    const float a_o   = (float)(sqrt(0.01) / sqrt((double)HID));
    const float r_o   = (float)sqrt(0.99);
    const float a_w2  = (float)(sqrt(0.5) / sqrt((double)(4 * HID)));
    const float b_w2  = (float)sqrt(0.5);
    const float r_w2  = (float)sqrt(0.5);

    // 0. convert wqkv/wo to fp16 (into mlp-region aliases; dead before step 10)
    cvt_w<<<(3 * HID * HID / 4 + 255) / 256, 256>>>((const float4*)wqkv, pWQKVH, 3 * HID * HID / 4);
    cvt_w<<<(HID * HID / 4 + 255) / 256, 256>>>((const float4*)wo, pWOH, HID * HID / 4);

    // 1. LN1 -> fp16
    ln_kernel<<<MTOK, 256>>>(x, ln1w, ln1b, pY);
    // 2. QKV = LN1(x) @ Wqkv^T * h^-0.5      [4096 x 6144] -> fp16
    gemm_tn<0, __half><<<dim3(48, 32, 1), 256, GEMM_SMEM>>>(
        pY, pWQKVH, pQKV, MTOK, 3 * HID, HID, 0, 0, 0,
        rs_h, nullptr, 0.f, nullptr, 0.f, 0.f);
    // 3. pack Q/K/Vt (fp16)
    pack_qkv<<<32768, 256>>>(pQKV, pQ, pK, pVT);
    // 4. scores = Q K^T * d^-0.5             [64 x 1024 x 1024] -> fp32
    gemm_tn<0, float><<<dim3(8, 8, BHTOT), 256, GEMM_SMEM>>>(
        pQ, pK, pS, SEQL, SEQL, DHEAD,
        (long)SEQL * DHEAD, (long)SEQL * DHEAD, (long)SEQL * SEQL,
        rs_d, nullptr, 0.f, nullptr, 0.f, 0.f);
    // 5. softmax: S(fp32) -> P(fp16)
    softmax_kernel<<<BHTOT * SEQL, 256>>>(pS, pP);
    // 5.5 S dead: convert w1/w2 (fp16) into the S region
    cvt_w<<<(4 * HID * HID / 4 + 255) / 256, 256>>>((const float4*)w1, pW1H, 4 * HID * HID / 4);
    cvt_w<<<(4 * HID * HID / 4 + 255) / 256, 256>>>((const float4*)w2, pW2H, 4 * HID * HID / 4);
    // 6. ctx = P @ V * sqrt(S)/sqrt(e)       [64 x 1024 x 128] -> fp16
    gemm_tn<0, __half><<<dim3(1, 8, BHTOT), 256, GEMM_SMEM>>>(
        pP, pVT, pCTX, SEQL, DHEAD, SEQL,
        (long)SEQL * SEQL, (long)SEQL * DHEAD, (long)SEQL * DHEAD,
        a_ctx, nullptr, 0.f, nullptr, 0.f, 0.f);
    // 7. repack ctx (fp16)
    repack_ctx<<<32768, 256>>>(pCTX, pCTXR);
    // 8. x2 = (ctx @ Wo^T)*h^-0.5*sqrt(tau) + x*sqrt(1-tau)  -> fp32
    gemm_tn<1, float><<<dim3(16, 32, 1), 256, GEMM_SMEM>>>(
        pCTXR, pWOH, pX2, MTOK, HID, HID, 0, 0, 0,
        a_o, nullptr, 0.f, x, r_o, 0.f);
    // 9. LN2 -> fp16
    ln_kernel<<<MTOK, 256>>>(pX2, ln2w, ln2b, pY);
    // 10. mlp = gelu_us( LN2 @ W1^T * h^-0.5 + b1 )  -> fp16
    gemm_tn<2, __half><<<dim3(64, 32, 1), 256, GEMM_SMEM>>>(
        pY, pW1H, pMLP, MTOK, 4 * HID, HID, 0, 0, 0,
        rs_h, b1, 1.0f, nullptr, 0.f, inv_rms);
    // 11. out = (mlp @ W2^T * (4h)^-0.5 + b2)*sqrt(.5) + x2*sqrt(.5)  -> fp32
    gemm_tn<3, float><<<dim3(16, 32, 1), 256, GEMM_SMEM>>>(
        pMLP, pW2H, out, MTOK, HID, 4 * HID, 0, 0, 0,
        a_w2, b2, b_w2, pX2, r_w2, 0.f);
}

// round 11
// speedup vs baseline: 2.3509x; 1.0621x over previous
#include <cuda_runtime.h>
#include <cuda_fp16.h>
#include <cmath>
#include <cstdint>

// ---------------- problem constants ----------------
#define HID   2048
#define SEQL  1024
#define NBAT  4
#define NHEAD 16
#define DHEAD 128
#define MTOK  4096          // NBAT*SEQL
#define BHTOT 64            // NBAT*NHEAD

#define MB ((size_t)1048576)

// ---------------- single flat scratch: 624MB --------------------------------
// Byte offsets (MB):
//   V     @16   (16)  fp16 packed V [bh,s,d] (from QKV epilogue)
//   Q     @64   (16)  fp16 ; K @80 (16) ; VT @96 (16)
//   S     @112  (128) fp16 scores (steps 4-5); W1H @112 (32) + W2H @144 (32)
//                     converted AFTER softmax (S dead)
//   P     @368  (128) fp16 probs
//   CTXR  @512  (16)  fp16 ctx in [token, hidden] (direct from ctx GEMM)
//   X2    @528  (32)  fp32 residual
//   MLP   @560  (64)  fp16 (step 10+); hosts WQKVH @560 (24) + WOH @584 (8)
__device__ __align__(16) unsigned char g_scratch[624 * MB];

#define OFF_V     (16 * MB)
#define OFF_Q     (64 * MB)
#define OFF_K     (80 * MB)
#define OFF_VT    (96 * MB)
#define OFF_S     (112 * MB)
#define OFF_W1H   (112 * MB)
#define OFF_W2H   (144 * MB)
#define OFF_P     (368 * MB)
#define OFF_CTXR  (512 * MB)
#define OFF_X2    (528 * MB)
#define OFF_MLP   (560 * MB)
#define OFF_WQKVH (560 * MB)
#define OFF_WOH   (584 * MB)

// ---------------- store helpers ---------------------------------------------
__device__ __forceinline__ void store2(float* C, long idx, float v0, float v1) {
    *(float2*)(C + idx) = make_float2(v0, v1);
}
__device__ __forceinline__ void store2(__half* C, long idx, float v0, float v1) {
    *(__half2*)(C + idx) = __floats2half2_rn(v0, v1);
}

__device__ __forceinline__ void ldsm4(unsigned* r, uint32_t a) {
    asm volatile("ldmatrix.sync.aligned.m8n8.x4.shared.b16 {%0,%1,%2,%3}, [%4];"
                 : "=r"(r[0]), "=r"(r[1]), "=r"(r[2]), "=r"(r[3]) : "r"(a));
}

// ---------------- GEMM: fp16 m16n8k16, 128x128 block, 8 warps, 64x32 tile ---
// C[m,n] = epilogue( alpha * sum_k A[m,k]*B[n,k] )  A: MxK fp16, B: NxK fp16
// BK=64, 2-stage cp.async, 2 CTAs/SM, ldmatrix fragment loads.
#define KP 72                              // halfs per smem row (64 + 8 pad)
#define STG_H ((128 + 128) * KP)           // 18432 halfs per stage
#define GEMM_SMEM (2 * STG_H * 2)          // 73728 B

// MODE 0: C = a*acc
// MODE 1: C = a*acc + rscale*resid
// MODE 2: C = gelu_us(a*acc + bscale*bias[n]) -> fp16
// MODE 3: C = a*acc + bscale*bias[n] + rscale*resid
// MODE 4: ctx->ctxr direct: write to [(z/16)*1024+r, (z%16)*128 + c] stride 2048
// MODE 5: qkv packed: col section 0/1/2 -> C(Q)/o2(K)/o3(V) at [bh,s,d]
template <int MODE, typename OUT_T>
__global__ void __launch_bounds__(256, 2)
gemm_tn(const __half* __restrict__ A, const __half* __restrict__ B,
        OUT_T* __restrict__ C,
        int M, int N, int K,
        long sA, long sB, long sC,
        float alpha,
        const float* __restrict__ bias, float bscale,
        const float* __restrict__ resid, float rscale,
        float inv_rms,
        __half* __restrict__ o2, __half* __restrict__ o3)
{
    extern __shared__ __half smh[];

    const int m0 = blockIdx.y * 128;
    const int n0 = blockIdx.x * 128;
    const int zz = blockIdx.z;
    A += zz * sA + (long)m0 * K;
    B += zz * sB + (long)n0 * K;
    C += zz * sC;
    const float* Rz = (MODE == 1 || MODE == 3) ? resid + zz * sC : nullptr;

    const int tid  = threadIdx.x;
    const int lane = tid & 31;
    const int warp = tid >> 5;
    const int wm = warp >> 2;          // 0..1 (64 rows)
    const int wn = warp & 3;           // 0..3 (32 cols)
    const int g  = lane >> 2;          // 0..7
    const int t4 = lane & 3;           // 0..3

    const int a_row = wm * 64 + (lane & 7) + ((lane >> 3) & 1) * 8;
    const int a_col = (lane >> 4) * 8;
    const int b_row = wn * 32 + (lane & 7) + ((lane >> 4) & 1) * 8;
    const int b_col = ((lane >> 3) & 1) * 8;

    const uint32_t smbase = (uint32_t)__cvta_generic_to_shared(smh);

    float acc[4][4][4];
#pragma unroll
    for (int i = 0; i < 4; i++)
#pragma unroll
        for (int j = 0; j < 4; j++)
#pragma unroll
            for (int c = 0; c < 4; c++) acc[i][j][c] = 0.f;

    const int KT = K / 64;

    auto issue = [&](int kt, int buf) {
        __half* Sb = smh + buf * STG_H;
        const long kof = (long)kt * 64;
#pragma unroll
        for (int q = 0; q < 8; q++) {
            int idx = tid + q * 256;
            if (idx < 1024) {
                int r = idx >> 3, c = (idx & 7) * 8;
                unsigned d = (unsigned)__cvta_generic_to_shared(&Sb[r * KP + c]);
                asm volatile("cp.async.cg.shared.global [%0], [%1], 16;\n"
                             :: "r"(d), "l"(A + (long)r * K + kof + c) : "memory");
            } else {
                int j = idx - 1024;
                int r = j >> 3, c = (j & 7) * 8;
                unsigned d = (unsigned)__cvta_generic_to_shared(&Sb[(128 + r) * KP + c]);
                asm volatile("cp.async.cg.shared.global [%0], [%1], 16;\n"
                             :: "r"(d), "l"(B + (long)r * K + kof + c) : "memory");
            }
        }
        asm volatile("cp.async.commit_group;\n" ::: "memory");
    };

    issue(0, 0);

    for (int kt = 0; kt < KT; kt++) {
        const int buf = kt & 1;
        asm volatile("cp.async.wait_group 0;\n" ::: "memory");
        __syncthreads();
        if (kt + 1 < KT) issue(kt + 1, buf ^ 1);

        const uint32_t abase = smbase + buf * (STG_H * 2);
        const uint32_t bbase = abase + 128 * KP * 2;

#pragma unroll
        for (int ks = 0; ks < 4; ks++) {
            const int kb = ks * 16;
            unsigned af[4][4], bf[4][2];
#pragma unroll
            for (int mt = 0; mt < 4; mt++)
                ldsm4(af[mt], abase + ((a_row + mt * 16) * KP + kb + a_col) * 2);
#pragma unroll
            for (int p = 0; p < 2; p++) {
                unsigned t[4];
                ldsm4(t, bbase + ((b_row + p * 16) * KP + kb + b_col) * 2);
                bf[2 * p][0] = t[0]; bf[2 * p][1] = t[1];
                bf[2 * p + 1][0] = t[2]; bf[2 * p + 1][1] = t[3];
            }
#pragma unroll
            for (int mt = 0; mt < 4; mt++)
#pragma unroll
                for (int nt = 0; nt < 4; nt++) {
                    asm volatile(
                        "mma.sync.aligned.m16n8k16.row.col.f32.f16.f16.f32 "
                        "{%0,%1,%2,%3}, {%4,%5,%6,%7}, {%8,%9}, {%0,%1,%2,%3};\n"
                        : "+f"(acc[mt][nt][0]), "+f"(acc[mt][nt][1]),
                          "+f"(acc[mt][nt][2]), "+f"(acc[mt][nt][3])
                        : "r"(af[mt][0]), "r"(af[mt][1]), "r"(af[mt][2]), "r"(af[mt][3]),
                          "r"(bf[nt][0]), "r"(bf[nt][1]));
                }
        }
    }

    // ---------------- epilogue ----------------
#pragma unroll
    for (int mt = 0; mt < 4; mt++) {
        int rbase = m0 + wm * 64 + mt * 16;
#pragma unroll
        for (int nt = 0; nt < 4; nt++) {
            int c0 = n0 + wn * 32 + nt * 8 + 2 * t4;
#pragma unroll
            for (int half_i = 0; half_i < 2; half_i++) {
                int r = rbase + g + half_i * 8;
                float v0 = acc[mt][nt][half_i * 2 + 0] * alpha;
                float v1 = acc[mt][nt][half_i * 2 + 1] * alpha;
                if (MODE == 2 || MODE == 3) {
                    v0 += bias[c0] * bscale;
                    v1 += bias[c0 + 1] * bscale;
                }
                if (MODE == 2) {
                    v0 = v0 * normcdff(v0) * inv_rms;
                    v1 = v1 * normcdff(v1) * inv_rms;
                }
                if (MODE == 5) {
                    // packed QKV write: section/head are block-uniform
                    const int zsec = c0 >> 11;
                    const int h = (c0 >> 7) & 15;
                    const int d = c0 & 127;
                    const int b = r >> 10, s = r & 1023;
                    long o = (((long)(b * NHEAD + h)) * SEQL + s) * DHEAD + d;
                    __half* dst = (zsec == 0) ? (__half*)C : (zsec == 1 ? o2 : o3);
                    *(__half2*)(dst + o) = __floats2half2_rn(v0, v1);
                } else if (MODE == 4) {
                    // ctx -> ctxr[b*S+s, h*128+d]
                    long o = (((long)(zz >> 4) * SEQL + r) * HID)
                           + (long)(zz & 15) * DHEAD + c0;
                    *(__half2*)((__half*)C + o) = __floats2half2_rn(v0, v1);
                } else {
                    long idx = (long)r * N + c0;
                    if (MODE == 1 || MODE == 3) {
                        float2 rv = *(const float2*)(Rz + idx);
                        v0 += rv.x * rscale;
                        v1 += rv.y * rscale;
                    }
                    store2(C, idx, v0, v1);
                }
            }
        }
    }
}

// ---------------- LayerNorm (fp32 in -> fp16 out) ---------------------------
__global__ void ln_kernel(const float* __restrict__ xin,
                          const float* __restrict__ w,
                          const float* __restrict__ b,
                          __half* __restrict__ y)
{
    __shared__ float red[16];
    const long row = blockIdx.x;
    const float4* xr = (const float4*)(xin + row * HID);
    const int t = threadIdx.x;

    float4 v0 = xr[t];
    float4 v1 = xr[t + 256];
    float s  = v0.x + v0.y + v0.z + v0.w + v1.x + v1.y + v1.z + v1.w;
    float sq = v0.x*v0.x + v0.y*v0.y + v0.z*v0.z + v0.w*v0.w
             + v1.x*v1.x + v1.y*v1.y + v1.z*v1.z + v1.w*v1.w;
#pragma unroll
    for (int o = 16; o; o >>= 1) {
        s  += __shfl_xor_sync(0xffffffffu, s,  o);
        sq += __shfl_xor_sync(0xffffffffu, sq, o);
    }
    if ((t & 31) == 0) { red[t >> 5] = s; red[8 + (t >> 5)] = sq; }
    __syncthreads();
    if (t == 0) {
        float S = 0.f, Q = 0.f;
        for (int i = 0; i < 8; i++) { S += red[i]; Q += red[8 + i]; }
        red[0] = S; red[8] = Q;
    }
    __syncthreads();
    const float mean = red[0] * (1.0f / HID);
    float var = red[8] * (1.0f / HID) - mean * mean;
    var = fmaxf(var, 0.0f);
    const float rstd = rsqrtf(var + 1e-5f);

    __half2* yh = (__half2*)(y + row * HID);
    const float4 w0 = ((const float4*)w)[t];
    const float4 w1 = ((const float4*)w)[t + 256];
    const float4 b0 = ((const float4*)b)[t];
    const float4 b1 = ((const float4*)b)[t + 256];
    yh[2 * t]           = __floats2half2_rn((v0.x - mean) * rstd * w0.x + b0.x,
                                            (v0.y - mean) * rstd * w0.y + b0.y);
    yh[2 * t + 1]       = __floats2half2_rn((v0.z - mean) * rstd * w0.z + b0.z,
                                            (v0.w - mean) * rstd * w0.w + b0.w);
    yh[512 + 2 * t]     = __floats2half2_rn((v1.x - mean) * rstd * w1.x + b1.x,
                                            (v1.y - mean) * rstd * w1.y + b1.y);
    yh[512 + 2 * t + 1] = __floats2half2_rn((v1.z - mean) * rstd * w1.z + b1.z,
                                            (v1.w - mean) * rstd * w1.w + b1.w);
}

// ---------------- softmax: fp16 scores -> fp16 probs ------------------------
__global__ void softmax_kernel(const __half* __restrict__ S, __half* __restrict__ P)
{
    __shared__ float red[16];
    const size_t row = blockIdx.x;
    const __half2* p = (const __half2*)(S + row * (size_t)SEQL);
    const int t = threadIdx.x;   // 256 threads, 4 halfs each

    float2 a = __half22float2(p[2 * t]);
    float2 b = __half22float2(p[2 * t + 1]);
    float mx = fmaxf(fmaxf(a.x, a.y), fmaxf(b.x, b.y));
#pragma unroll
    for (int o = 16; o; o >>= 1) mx = fmaxf(mx, __shfl_xor_sync(0xffffffffu, mx, o));
    if ((t & 31) == 0) red[t >> 5] = mx;
    __syncthreads();
    if (t == 0) {
        float m = red[0];
        for (int i = 1; i < 8; i++) m = fmaxf(m, red[i]);
        red[0] = m;
    }
    __syncthreads();
    mx = red[0];

    float e0 = expf(a.x - mx), e1 = expf(a.y - mx);
    float e2 = expf(b.x - mx), e3 = expf(b.y - mx);
    float s = e0 + e1 + e2 + e3;
#pragma unroll
    for (int o = 16; o; o >>= 1) s += __shfl_xor_sync(0xffffffffu, s, o);
    if ((t & 31) == 0) red[8 + (t >> 5)] = s;
    __syncthreads();
    if (t == 0) {
        float S2 = 0.f;
        for (int i = 0; i < 8; i++) S2 += red[8 + i];
        red[8] = S2;
    }
    __syncthreads();
    const float inv = 1.0f / red[8];

    __half2* ph = (__half2*)(P + row * (size_t)SEQL);
    ph[2 * t]     = __floats2half2_rn(e0 * inv, e1 * inv);
    ph[2 * t + 1] = __floats2half2_rn(e2 * inv, e3 * inv);
}

// ---------------- V[bh,s,d] -> Vt[bh,d,s] transpose -------------------------
__global__ void transpose_v(const __half* __restrict__ V, __half* __restrict__ Vt)
{
    __shared__ __half tile[32][33];
    const int bh = blockIdx.z;
    const int s0 = blockIdx.x * 32, d0 = blockIdx.y * 32;
    const __half* src = V + (long)bh * SEQL * DHEAD;
    __half* dst = Vt + (long)bh * SEQL * DHEAD;
    const int tx = threadIdx.x, ty = threadIdx.y;  // 32 x 8
#pragma unroll
    for (int i = 0; i < 32; i += 8)
        tile[ty + i][tx] = src[(long)(s0 + ty + i) * DHEAD + d0 + tx];
    __syncthreads();
#pragma unroll
    for (int i = 0; i < 32; i += 8)
        dst[(long)(d0 + ty + i) * SEQL + s0 + tx] = tile[tx][ty + i];
}

// ---------------- weight conversion fp32 -> fp16 ----------------------------
__global__ void cvt_w(const float4* __restrict__ in, __half* __restrict__ out, int n4)
{
    int i = blockIdx.x * 256 + threadIdx.x;
    if (i < n4) {
        float4 v = in[i];
        __half2* o = (__half2*)(out + (size_t)i * 4);
        o[0] = __floats2half2_rn(v.x, v.y);
        o[1] = __floats2half2_rn(v.z, v.w);
    }
}

// ---------------- launch ----------------------------------------------------
extern "C" void kernel_launch(void* const* d_in, const int* in_sizes, int n_in,
                              void* d_out, int out_size)
{
    const float* x    = (const float*)d_in[0];
    const float* ln1w = (const float*)d_in[1];
    const float* ln1b = (const float*)d_in[2];
    const float* wqkv = (const float*)d_in[3];
    const float* wo   = (const float*)d_in[4];
    const float* ln2w = (const float*)d_in[5];
    const float* ln2b = (const float*)d_in[6];
    const float* w1   = (const float*)d_in[7];
    const float* b1   = (const float*)d_in[8];
    const float* w2   = (const float*)d_in[9];
    const float* b2   = (const float*)d_in[10];
    float* out = (float*)d_out;

    // GELU_RMS via the same quadrature as the reference
    double ssum = 0.0;
    const double dx = 24.0 / 48000.0;
    for (int i = 0; i <= 48000; i++) {
        double xx  = -12.0 + dx * i;
        double pdf = exp(-0.5 * xx * xx) / sqrt(2.0 * M_PI);
        double cdf = 0.5 * (1.0 + erf(xx / sqrt(2.0)));
        double gg  = xx * cdf;
        ssum += gg * gg * pdf;
    }
    const float inv_rms = (float)(1.0 / sqrt(ssum * dx));

    unsigned char* base;
    cudaGetSymbolAddress((void**)&base, g_scratch);
    __half* pV     = (__half*)(base + OFF_V);
    __half* pQ     = (__half*)(base + OFF_Q);
    __half* pK     = (__half*)(base + OFF_K);
    __half* pVT    = (__half*)(base + OFF_VT);
    __half* pS     = (__half*)(base + OFF_S);
    __half* pW1H   = (__half*)(base + OFF_W1H);
    __half* pW2H   = (__half*)(base + OFF_W2H);
    __half* pP     = (__half*)(base + OFF_P);
    __half* pCTXR  = (__half*)(base + OFF_CTXR);
    float*  pX2    = (float*) (base + OFF_X2);
    __half* pMLP   = (__half*)(base + OFF_MLP);
    __half* pWQKVH = (__half*)(base + OFF_WQKVH);
    __half* pWOH   = (__half*)(base + OFF_WOH);

    cudaFuncSetAttribute(gemm_tn<0, __half>, cudaFuncAttributeMaxDynamicSharedMemorySize, GEMM_SMEM);
    cudaFuncSetAttribute(gemm_tn<1, float>,  cudaFuncAttributeMaxDynamicSharedMemorySize, GEMM_SMEM);
    cudaFuncSetAttribute(gemm_tn<2, __half>, cudaFuncAttributeMaxDynamicSharedMemorySize, GEMM_SMEM);
    cudaFuncSetAttribute(gemm_tn<3, float>,  cudaFuncAttributeMaxDynamicSharedMemorySize, GEMM_SMEM);
    cudaFuncSetAttribute(gemm_tn<4, __half>, cudaFuncAttributeMaxDynamicSharedMemorySize, GEMM_SMEM);
    cudaFuncSetAttribute(gemm_tn<5, __half>, cudaFuncAttributeMaxDynamicSharedMemorySize, GEMM_SMEM);

    const float rs_h  = (float)(1.0 / sqrt((double)HID));
    const float rs_d  = (float)(1.0 / sqrt((double)DHEAD));
    const float a_ctx = (float)(32.0 / exp(0.5));
    const float a_o   = (float)(sqrt(0.01) / sqrt((double)HID));
    const float r_o   = (float)sqrt(0.99);
    const float a_w2  = (float)(sqrt(0.5) / sqrt((double)(4 * HID)));
    const float b_w2  = (float)sqrt(0.5);
    const float r_w2  = (float)sqrt(0.5);

    // 0. convert wqkv/wo to fp16 (into mlp-region aliases; dead before step 10)
    cvt_w<<<(3 * HID * HID / 4 + 255) / 256, 256>>>((const float4*)wqkv, pWQKVH, 3 * HID * HID / 4);
    cvt_w<<<(HID * HID / 4 + 255) / 256, 256>>>((const float4*)wo, pWOH, HID * HID / 4);

    // 1. LN1 -> fp16
    ln_kernel<<<MTOK, 256>>>(x, ln1w, ln1b, (__half*)(base + 0));  // Y at offset 0
    __half* pY = (__half*)(base + 0);
    // 2. QKV GEMM writes packed Q/K/V directly (MODE 5)
    gemm_tn<5, __half><<<dim3(48, 32, 1), 256, GEMM_SMEM>>>(
        pY, pWQKVH, pQ, MTOK, 3 * HID, HID, 0, 0, 0,
        rs_h, nullptr, 0.f, nullptr, 0.f, 0.f, pK, pV);
    // 3. Vt = transpose(V)
    transpose_v<<<dim3(32, 4, BHTOT), dim3(32, 8)>>>(pV, pVT);
    // 4. scores = Q K^T * d^-0.5  -> fp16
    gemm_tn<0, __half><<<dim3(8, 8, BHTOT), 256, GEMM_SMEM>>>(
        pQ, pK, pS, SEQL, SEQL, DHEAD,
        (long)SEQL * DHEAD, (long)SEQL * DHEAD, (long)SEQL * SEQL,
        rs_d, nullptr, 0.f, nullptr, 0.f, 0.f, nullptr, nullptr);
    // 5. softmax: S(fp16) -> P(fp16)
    softmax_kernel<<<BHTOT * SEQL, 256>>>(pS, pP);
    // 5.5 S dead: convert w1/w2 into the S region
    cvt_w<<<(4 * HID * HID / 4 + 255) / 256, 256>>>((const float4*)w1, pW1H, 4 * HID * HID / 4);
    cvt_w<<<(4 * HID * HID / 4 + 255) / 256, 256>>>((const float4*)w2, pW2H, 4 * HID * HID / 4);
    // 6. ctx = P @ V -> ctxr directly (MODE 4)
    gemm_tn<4, __half><<<dim3(1, 8, BHTOT), 256, GEMM_SMEM>>>(
        pP, pVT, pCTXR, SEQL, DHEAD, SEQL,
        (long)SEQL * SEQL, (long)SEQL * DHEAD, 0,
        a_ctx, nullptr, 0.f, nullptr, 0.f, 0.f, nullptr, nullptr);
    // 7. x2 = (ctx @ Wo^T)*h^-0.5*sqrt(tau) + x*sqrt(1-tau)  -> fp32
    gemm_tn<1, float><<<dim3(16, 32, 1), 256, GEMM_SMEM>>>(
        pCTXR, pWOH, pX2, MTOK, HID, HID, 0, 0, 0,
        a_o, nullptr, 0.f, x, r_o, 0.f, nullptr, nullptr);
    // 8. LN2 -> fp16
    ln_kernel<<<MTOK, 256>>>(pX2, ln2w, ln2b, pY);
    // 9. mlp = gelu_us( LN2 @ W1^T * h^-0.5 + b1 )  -> fp16
    gemm_tn<2, __half><<<dim3(64, 32, 1), 256, GEMM_SMEM>>>(
        pY, pW1H, pMLP, MTOK, 4 * HID, HID, 0, 0, 0,
        rs_h, b1, 1.0f, nullptr, 0.f, inv_rms, nullptr, nullptr);
    // 10. out = (mlp @ W2^T * (4h)^-0.5 + b2)*sqrt(.5) + x2*sqrt(.5)  -> fp32
    gemm_tn<3, float><<<dim3(16, 32, 1), 256, GEMM_SMEM>>>(
        pMLP, pW2H, out, MTOK, HID, 4 * HID, 0, 0, 0,
        a_w2, b2, b_w2, pX2, r_w2, 0.f, nullptr, nullptr);
}